// round 7
// baseline (speedup 1.0000x reference)
#include <cuda_runtime.h>
#include <cstdint>
#include <cstddef>

#define BB 4
#define SS 2048
#define DM 1024
#define NH 16
#define DK 64

// Scratch (allocation-free rule: __device__ globals)
__device__ float g_Pq[BB * SS * DM];
__device__ float g_Pk[BB * SS * DM];
__device__ float g_Pv[BB * SS * DM];
__device__ float g_ctxT[BB * SS * DM];
__device__ float g_fc[BB * SS * DM];
__device__ float g_attn_fallback[(size_t)BB * NH * SS * SS];

__device__ __forceinline__ uint32_t su(const void* p) {
  return (uint32_t)__cvta_generic_to_shared(p);
}
__device__ __forceinline__ void cpa16(uint32_t s, const void* g) {
  asm volatile("cp.async.cg.shared.global [%0], [%1], 16;\n" ::"r"(s), "l"(g));
}
__device__ __forceinline__ void cpcommit() {
  asm volatile("cp.async.commit_group;\n");
}
template <int N>
__device__ __forceinline__ void cpwait() {
  asm volatile("cp.async.wait_group %0;\n" ::"n"(N));
}
__device__ __forceinline__ void ldsm4(uint32_t& r0, uint32_t& r1, uint32_t& r2,
                                      uint32_t& r3, uint32_t a) {
  asm volatile(
      "ldmatrix.sync.aligned.m8n8.x4.shared.b16 {%0,%1,%2,%3},[%4];\n"
      : "=r"(r0), "=r"(r1), "=r"(r2), "=r"(r3)
      : "r"(a));
}
__device__ __forceinline__ void mma_tf32(float* c, uint32_t a0, uint32_t a1,
                                         uint32_t a2, uint32_t a3, uint32_t b0,
                                         uint32_t b1) {
  asm volatile(
      "mma.sync.aligned.m16n8k8.row.col.f32.tf32.tf32.f32 "
      "{%0,%1,%2,%3},{%4,%5,%6,%7},{%8,%9},{%0,%1,%2,%3};\n"
      : "+f"(c[0]), "+f"(c[1]), "+f"(c[2]), "+f"(c[3])
      : "r"(a0), "r"(a1), "r"(a2), "r"(a3), "r"(b0), "r"(b1));
}

// ---------------------------------------------------------------------------
// tf32 GEMM (NT): C[M,N] = A[M,K] * W[N,K]^T. 128x128 tile, BK=32, 8 warps
// (warp 32x64). cp.async double-buffered stages; ldmatrix fragment loads.
// smem stride 36 words (144B): 16B-divisible for LDGSTS; 4r mod 32 bank
// pattern -> conflict-free ldmatrix.
// ---------------------------------------------------------------------------
#define GST 36
#define GSTAGE (128 * GST)  // words per tile stage
#define GEMM_SMEM (4 * GSTAGE * 4)

__global__ __launch_bounds__(256) void gemm_tf32_nt(
    const float* __restrict__ A, const float* __restrict__ Bw,
    float* __restrict__ C, int M, int N, int K) {
  extern __shared__ float sm[];
  float* As = sm;               // [2][GSTAGE]
  float* Bs = sm + 2 * GSTAGE;  // [2][GSTAGE]
  int tid = threadIdx.x, lane = tid & 31, wid = tid >> 5;
  int bm = blockIdx.y * 128, bn = blockIdx.x * 128;
  int m0 = (wid & 3) * 32, n0 = (wid >> 2) * 64;
  int sub = lane >> 3, l7 = lane & 7;
  int g = lane >> 2, tg = lane & 3;

  uint32_t sAs = su(As), sBs = su(Bs);

  // ldmatrix lane base offsets (bytes)
  // A frag (m16k8): rows m0+mt*16+(sub&1)*8+l7, col half (sub>>1)*4
  uint32_t aOff = ((m0 + (sub & 1) * 8 + l7) * GST + (sub >> 1) * 4) * 4;
  // B frag (two n-tiles): rows n0+p*16+(sub>>1)*8+l7, col half (sub&1)*4
  uint32_t bOff = ((n0 + (sub >> 1) * 8 + l7) * GST + (sub & 1) * 4) * 4;

  float c[2][8][4];
#pragma unroll
  for (int mt = 0; mt < 2; mt++)
#pragma unroll
    for (int nt = 0; nt < 8; nt++)
#pragma unroll
      for (int j = 0; j < 4; j++) c[mt][nt][j] = 0.f;

  // prologue: stage 0 and stage 1 in flight
#pragma unroll
  for (int pre = 0; pre < 2; pre++) {
    int k0 = pre * 32;
#pragma unroll
    for (int i = 0; i < 4; i++) {
      int cc = tid + i * 256;
      int mrow = cc >> 3;
      int k4 = (cc & 7) << 2;
      cpa16(sAs + (pre * GSTAGE + mrow * GST + k4) * 4,
            A + (size_t)(bm + mrow) * K + k0 + k4);
      cpa16(sBs + (pre * GSTAGE + mrow * GST + k4) * 4,
            Bw + (size_t)(bn + mrow) * K + k0 + k4);
    }
    cpcommit();
  }

  int NIT = K / 32;
  for (int kt = 0; kt < NIT; kt++) {
    if (kt < NIT - 1) cpwait<1>();
    else cpwait<0>();
    __syncthreads();
    int st = kt & 1;
    uint32_t aBase = sAs + st * GSTAGE * 4 + aOff;
    uint32_t bBase = sBs + st * GSTAGE * 4 + bOff;
#pragma unroll
    for (int kk = 0; kk < 4; kk++) {
      uint32_t a0[4], a1[4], b[4][4];
      ldsm4(a0[0], a0[1], a0[2], a0[3], aBase + kk * 32);
      ldsm4(a1[0], a1[1], a1[2], a1[3], aBase + 16 * GST * 4 + kk * 32);
#pragma unroll
      for (int p = 0; p < 4; p++)
        ldsm4(b[p][0], b[p][1], b[p][2], b[p][3],
              bBase + p * 16 * GST * 4 + kk * 32);
#pragma unroll
      for (int p = 0; p < 4; p++) {
        mma_tf32(c[0][2 * p], a0[0], a0[1], a0[2], a0[3], b[p][0], b[p][1]);
        mma_tf32(c[0][2 * p + 1], a0[0], a0[1], a0[2], a0[3], b[p][2], b[p][3]);
        mma_tf32(c[1][2 * p], a1[0], a1[1], a1[2], a1[3], b[p][0], b[p][1]);
        mma_tf32(c[1][2 * p + 1], a1[0], a1[1], a1[2], a1[3], b[p][2], b[p][3]);
      }
    }
    __syncthreads();
    if (kt + 2 < NIT) {
      int k0 = (kt + 2) * 32;
#pragma unroll
      for (int i = 0; i < 4; i++) {
        int cc = tid + i * 256;
        int mrow = cc >> 3;
        int k4 = (cc & 7) << 2;
        cpa16(sAs + (st * GSTAGE + mrow * GST + k4) * 4,
              A + (size_t)(bm + mrow) * K + k0 + k4);
        cpa16(sBs + (st * GSTAGE + mrow * GST + k4) * 4,
              Bw + (size_t)(bn + mrow) * K + k0 + k4);
      }
      cpcommit();
    }
  }

#pragma unroll
  for (int mt = 0; mt < 2; mt++)
#pragma unroll
    for (int nt = 0; nt < 8; nt++) {
      int row0 = bm + m0 + mt * 16 + g;
      int col = bn + n0 + nt * 8 + 2 * tg;
      *(float2*)&C[(size_t)row0 * N + col] =
          make_float2(c[mt][nt][0], c[mt][nt][1]);
      *(float2*)&C[(size_t)(row0 + 8) * N + col] =
          make_float2(c[mt][nt][2], c[mt][nt][3]);
    }
}

// ---------------------------------------------------------------------------
// Attention. Per (b,h), 64 Q-rows per block, 64-col K tiles.
// cp.async double-buffered K; V transposed through registers (LDG one tile
// early); ldmatrix fragments everywhere; rowsums in registers reduced once.
// smem words (stride 68 = 272B, LDGSTS- and ldmatrix-clean):
//   Qs 0, Ks[2] at 4352/8704, Vt 13056, Es 17408 -> 21760 words (87KB).
// ---------------------------------------------------------------------------
#define AST 68
#define QS_W 0
#define KS_W 4352
#define VT_W 13056
#define ES_W 17408
#define ATTN_SMEM (21760 * 4)

__global__ __launch_bounds__(256) void attn_kernel(
    const float* __restrict__ Pq, const float* __restrict__ Pk,
    const float* __restrict__ Pv, float* __restrict__ attn,
    float* __restrict__ ctxT) {
  extern __shared__ float smf[];
  __shared__ float lsum[64];

  int tid = threadIdx.x, lane = tid & 31, wid = tid >> 5;
  int sub = lane >> 3, l7 = lane & 7;
  int g = lane >> 2, tg = lane & 3;
  int m0 = (wid & 3) * 16, n0 = (wid >> 2) * 32;
  int qt = blockIdx.x;
  int bh = blockIdx.y;
  int b = bh >> 4, h = bh & 15;

  const float* Qb = Pq + (size_t)b * SS * DM + (size_t)h * SS * DK;
  const float* Kb = Pk + (size_t)b * SS * DM + (size_t)h * SS * DK;
  const float* Vb = Pv + (size_t)b * SS * DM + (size_t)h * SS * DK;
  float* attn_b = attn + ((size_t)bh * SS + (size_t)qt * 64) * SS;

  uint32_t sbase = su(smf);

  // ldmatrix lane bases (bytes)
  uint32_t qOff = sbase + ((QS_W + (m0 + (sub & 1) * 8 + l7) * AST) +
                           (sub >> 1) * 4) * 4;
  uint32_t eOff = sbase + ((ES_W + (m0 + (sub & 1) * 8 + l7) * AST) +
                           (sub >> 1) * 4) * 4;
  // B frags: rows n0+p*16+(sub>>1)*8+l7, col half (sub&1)*4
  uint32_t kOffR = ((n0 + (sub >> 1) * 8 + l7) * AST + (sub & 1) * 4) * 4;
  uint32_t vOff = sbase + (VT_W * 4) + kOffR;

  // cp.async mapping: 1024 chunks (64 rows x 16 chunks), 4 per thread
  int crow[4], ccol[4];
#pragma unroll
  for (int i = 0; i < 4; i++) {
    int cc = tid + i * 256;
    crow[i] = cc >> 4;
    ccol[i] = (cc & 15) << 2;
  }

  // prologue: Q + K tile 0 in one group
#pragma unroll
  for (int i = 0; i < 4; i++) {
    cpa16(sbase + ((QS_W + crow[i] * AST + ccol[i])) * 4,
          Qb + (size_t)(qt * 64 + crow[i]) * DK + ccol[i]);
    cpa16(sbase + ((KS_W + crow[i] * AST + ccol[i])) * 4,
          Kb + (size_t)(crow[i]) * DK + ccol[i]);
  }
  cpcommit();

  // prologue: V tile 0 into registers
  int lr = tid >> 2;            // V row (c) 0..63
  int lc = (tid & 3) << 2;      // V col (d) base
  float4 vv[4];
#pragma unroll
  for (int p = 0; p < 4; p++)
    vv[p] = *(const float4*)&Vb[(size_t)lr * DK + lc + p * 16];

  if (tid < 64) lsum[tid] = 0.f;

  float o[4][4];
#pragma unroll
  for (int nt = 0; nt < 4; nt++)
#pragma unroll
    for (int j = 0; j < 4; j++) o[nt][j] = 0.f;
  float racc0 = 0.f, racc1 = 0.f;

  for (int kt = 0; kt < SS / 64; kt++) {
    int st = kt & 1;
    cpwait<0>();
    __syncthreads();  // K(kt) ready; all warps done with Es/Vt of kt-1

    // prefetch K(kt+1) into other stage
    if (kt + 1 < SS / 64) {
#pragma unroll
      for (int i = 0; i < 4; i++)
        cpa16(sbase + ((KS_W + (st ^ 1) * 4352 + crow[i] * AST + ccol[i])) * 4,
              Kb + (size_t)((kt + 1) * 64 + crow[i]) * DK + ccol[i]);
      cpcommit();
    }

    // store Vt (transpose) from regs, then prefetch V(kt+1) into regs
#pragma unroll
    for (int p = 0; p < 4; p++) {
      float vr[4] = {vv[p].x, vv[p].y, vv[p].z, vv[p].w};
#pragma unroll
      for (int j = 0; j < 4; j++)
        smf[VT_W + (lc + p * 16 + j) * AST + lr] = vr[j];
    }
    if (kt + 1 < SS / 64) {
#pragma unroll
      for (int p = 0; p < 4; p++)
        vv[p] = *(const float4*)&Vb[(size_t)((kt + 1) * 64 + lr) * DK + lc +
                                    p * 16];
    }

    // S = Q K^T
    float s[4][4];
#pragma unroll
    for (int nt = 0; nt < 4; nt++)
#pragma unroll
      for (int j = 0; j < 4; j++) s[nt][j] = 0.f;
    uint32_t kBase = sbase + (KS_W + st * 4352) * 4 + kOffR;
#pragma unroll
    for (int kk = 0; kk < 8; kk++) {
      uint32_t a[4], b0[4], b1[4];
      ldsm4(a[0], a[1], a[2], a[3], qOff + kk * 32);
      ldsm4(b0[0], b0[1], b0[2], b0[3], kBase + kk * 32);
      ldsm4(b1[0], b1[1], b1[2], b1[3], kBase + 16 * AST * 4 + kk * 32);
      mma_tf32(s[0], a[0], a[1], a[2], a[3], b0[0], b0[1]);
      mma_tf32(s[1], a[0], a[1], a[2], a[3], b0[2], b0[3]);
      mma_tf32(s[2], a[0], a[1], a[2], a[3], b1[0], b1[1]);
      mma_tf32(s[3], a[0], a[1], a[2], a[3], b1[2], b1[3]);
    }

    // exp, write unnormalized attn, stash Es, accumulate row sums
    int row0 = m0 + g, row1 = m0 + g + 8;
#pragma unroll
    for (int nt = 0; nt < 4; nt++) {
      float e0 = __expf(s[nt][0] * 0.125f);
      float e1 = __expf(s[nt][1] * 0.125f);
      float e2 = __expf(s[nt][2] * 0.125f);
      float e3 = __expf(s[nt][3] * 0.125f);
      racc0 += e0 + e1;
      racc1 += e2 + e3;
      int cc = n0 + nt * 8 + 2 * tg;
      *(float2*)&attn_b[(size_t)row0 * SS + kt * 64 + cc] = make_float2(e0, e1);
      *(float2*)&attn_b[(size_t)row1 * SS + kt * 64 + cc] = make_float2(e2, e3);
      *(float2*)&smf[ES_W + row0 * AST + cc] = make_float2(e0, e1);
      *(float2*)&smf[ES_W + row1 * AST + cc] = make_float2(e2, e3);
    }
    __syncthreads();  // Es + Vt visible

    // ctx += E @ V
#pragma unroll
    for (int kk = 0; kk < 8; kk++) {
      uint32_t a[4], b0[4], b1[4];
      ldsm4(a[0], a[1], a[2], a[3], eOff + kk * 32);
      ldsm4(b0[0], b0[1], b0[2], b0[3], vOff + kk * 32);
      ldsm4(b1[0], b1[1], b1[2], b1[3], vOff + 16 * AST * 4 + kk * 32);
      mma_tf32(o[0], a[0], a[1], a[2], a[3], b0[0], b0[1]);
      mma_tf32(o[1], a[0], a[1], a[2], a[3], b0[2], b0[3]);
      mma_tf32(o[2], a[0], a[1], a[2], a[3], b1[0], b1[1]);
      mma_tf32(o[3], a[0], a[1], a[2], a[3], b1[2], b1[3]);
    }
  }

  // reduce row sums (each m-row covered by two warps: wid and wid+4)
  racc0 += __shfl_xor_sync(0xffffffffu, racc0, 1);
  racc0 += __shfl_xor_sync(0xffffffffu, racc0, 2);
  racc1 += __shfl_xor_sync(0xffffffffu, racc1, 1);
  racc1 += __shfl_xor_sync(0xffffffffu, racc1, 2);
  if (tg == 0) {
    atomicAdd(&lsum[m0 + g], racc0);
    atomicAdd(&lsum[m0 + g + 8], racc1);
  }
  __syncthreads();

  // normalize ctx, write [b, s, h*64 + d]
  {
    int row0 = m0 + g, row1 = m0 + g + 8;
    float rl0 = 1.f / lsum[row0];
    float rl1 = 1.f / lsum[row1];
#pragma unroll
    for (int nt = 0; nt < 4; nt++) {
      int col = h * DK + n0 + nt * 8 + 2 * tg;
      *(float2*)&g_ctxT[(size_t)b * SS * DM + (size_t)(qt * 64 + row0) * DM +
                        col] = make_float2(o[nt][0] * rl0, o[nt][1] * rl0);
      *(float2*)&g_ctxT[(size_t)b * SS * DM + (size_t)(qt * 64 + row1) * DM +
                        col] = make_float2(o[nt][2] * rl1, o[nt][3] * rl1);
    }
  }
  (void)ctxT;

  // rescale attn stripe in place (rows hot in L2)
  for (int idx = tid; idx < 64 * (SS / 4); idx += 256) {
    int r = idx / (SS / 4);
    int c4 = idx % (SS / 4);
    float sc = 1.f / lsum[r];
    float4* p = (float4*)&attn_b[(size_t)r * SS + c4 * 4];
    float4 vvv = *p;
    vvv.x *= sc; vvv.y *= sc; vvv.z *= sc; vvv.w *= sc;
    *p = vvv;
  }
}

// ---------------------------------------------------------------------------
// Residual add + LayerNorm, one block per row.
// ---------------------------------------------------------------------------
__global__ __launch_bounds__(256) void add_ln_kernel(
    const float* __restrict__ fc, const float* __restrict__ res,
    const float* __restrict__ gamma, const float* __restrict__ beta,
    float* __restrict__ out) {
  int row = blockIdx.x;
  int tid = threadIdx.x;
  float4 xf = ((const float4*)(fc + (size_t)row * DM))[tid];
  float4 xr = ((const float4*)(res + (size_t)row * DM))[tid];
  float x0 = xf.x + xr.x, x1 = xf.y + xr.y, x2 = xf.z + xr.z, x3 = xf.w + xr.w;
  float s = x0 + x1 + x2 + x3;
  float sq = x0 * x0 + x1 * x1 + x2 * x2 + x3 * x3;
#pragma unroll
  for (int o = 16; o; o >>= 1) {
    s += __shfl_down_sync(0xffffffffu, s, o);
    sq += __shfl_down_sync(0xffffffffu, sq, o);
  }
  __shared__ float ws[8], wq[8];
  __shared__ float mu_s, rs_s;
  if ((tid & 31) == 0) { ws[tid >> 5] = s; wq[tid >> 5] = sq; }
  __syncthreads();
  if (tid == 0) {
    float St = 0.f, Qt = 0.f;
#pragma unroll
    for (int i = 0; i < 8; i++) { St += ws[i]; Qt += wq[i]; }
    float mu = St * (1.f / DM);
    float var = Qt * (1.f / DM) - mu * mu;
    mu_s = mu;
    rs_s = rsqrtf(var + 1e-6f);
  }
  __syncthreads();
  float mu = mu_s, rs = rs_s;
  float4 g = ((const float4*)gamma)[tid];
  float4 bb = ((const float4*)beta)[tid];
  float4 o;
  o.x = (x0 - mu) * rs * g.x + bb.x;
  o.y = (x1 - mu) * rs * g.y + bb.y;
  o.z = (x2 - mu) * rs * g.z + bb.z;
  o.w = (x3 - mu) * rs * g.w + bb.w;
  ((float4*)(out + (size_t)row * DM))[tid] = o;
}

// ---------------------------------------------------------------------------
extern "C" void kernel_launch(void* const* d_in, const int* in_sizes, int n_in,
                              void* d_out, int out_size) {
  const float* q = (const float*)d_in[0];
  const float* k = (const float*)d_in[1];
  const float* v = (const float*)d_in[2];
  const float* w_qs = (const float*)d_in[3];
  const float* w_ks = (const float*)d_in[4];
  const float* w_vs = (const float*)d_in[5];
  const float* w_fc = (const float*)d_in[6];
  const float* gamma = (const float*)d_in[7];
  const float* beta = (const float*)d_in[8];
  float* out = (float*)d_out;

  const size_t out_elems = (size_t)BB * SS * DM;                // 8388608
  const size_t attn_elems = (size_t)BB * NH * SS * (size_t)SS;  // 268435456
  float* attn = ((size_t)out_size >= out_elems + attn_elems)
                    ? out + out_elems
                    : nullptr;

  float *Pq, *Pk, *Pv, *ctxT, *fcb, *attn_fb;
  cudaGetSymbolAddress((void**)&Pq, g_Pq);
  cudaGetSymbolAddress((void**)&Pk, g_Pk);
  cudaGetSymbolAddress((void**)&Pv, g_Pv);
  cudaGetSymbolAddress((void**)&ctxT, g_ctxT);
  cudaGetSymbolAddress((void**)&fcb, g_fc);
  cudaGetSymbolAddress((void**)&attn_fb, g_attn_fallback);
  if (!attn) attn = attn_fb;

  cudaFuncSetAttribute(gemm_tf32_nt,
                       cudaFuncAttributeMaxDynamicSharedMemorySize, GEMM_SMEM);
  cudaFuncSetAttribute(attn_kernel,
                       cudaFuncAttributeMaxDynamicSharedMemorySize, ATTN_SMEM);

  dim3 gproj(DM / 128, (BB * SS) / 128);  // (8, 64)
  gemm_tf32_nt<<<gproj, 256, GEMM_SMEM>>>(q, w_qs, Pq, BB * SS, DM, DM);
  gemm_tf32_nt<<<gproj, 256, GEMM_SMEM>>>(k, w_ks, Pk, BB * SS, DM, DM);
  gemm_tf32_nt<<<gproj, 256, GEMM_SMEM>>>(v, w_vs, Pv, BB * SS, DM, DM);

  attn_kernel<<<dim3(SS / 64, BB * NH), 256, ATTN_SMEM>>>(Pq, Pk, Pv, attn,
                                                          ctxT);

  gemm_tf32_nt<<<gproj, 256, GEMM_SMEM>>>(ctxT, w_fc, fcb, BB * SS, DM, DM);
  add_ln_kernel<<<BB * SS, 256>>>(fcb, q, gamma, beta, out);
}

// round 9
// speedup vs baseline: 1.3158x; 1.3158x over previous
#include <cuda_runtime.h>
#include <cstdint>
#include <cstddef>

#define BB 4
#define SS 2048
#define DM 1024
#define NH 16
#define DK 64

// Scratch (allocation-free rule: __device__ globals)
__device__ float g_Pq[BB * SS * DM];
__device__ float g_Pk[BB * SS * DM];
__device__ float g_Pv[BB * SS * DM];
__device__ float g_ctxT[BB * SS * DM];
__device__ float g_fc[BB * SS * DM];
__device__ float g_attn_fallback[(size_t)BB * NH * SS * SS];

__device__ __forceinline__ uint32_t f2tf(float x) {
  uint32_t u;
  asm("cvt.rna.tf32.f32 %0, %1;" : "=r"(u) : "f"(x));
  return u;
}
__device__ __forceinline__ uint32_t tfr(uint32_t x) {  // RNA-round raw fp32 bits
  uint32_t u;
  asm("cvt.rna.tf32.f32 %0, %1;" : "=r"(u) : "f"(__uint_as_float(x)));
  return u;
}
__device__ __forceinline__ uint32_t su(const void* p) {
  return (uint32_t)__cvta_generic_to_shared(p);
}
__device__ __forceinline__ void cpa16(uint32_t s, const void* g) {
  asm volatile("cp.async.cg.shared.global [%0], [%1], 16;\n" ::"r"(s), "l"(g));
}
__device__ __forceinline__ void cpcommit() {
  asm volatile("cp.async.commit_group;\n");
}
template <int N>
__device__ __forceinline__ void cpwait() {
  asm volatile("cp.async.wait_group %0;\n" ::"n"(N));
}
__device__ __forceinline__ void ldsm4(uint32_t& r0, uint32_t& r1, uint32_t& r2,
                                      uint32_t& r3, uint32_t a) {
  asm volatile(
      "ldmatrix.sync.aligned.m8n8.x4.shared.b16 {%0,%1,%2,%3},[%4];\n"
      : "=r"(r0), "=r"(r1), "=r"(r2), "=r"(r3)
      : "r"(a));
}
__device__ __forceinline__ void mma_tf32(float* c, uint32_t a0, uint32_t a1,
                                         uint32_t a2, uint32_t a3, uint32_t b0,
                                         uint32_t b1) {
  asm volatile(
      "mma.sync.aligned.m16n8k8.row.col.f32.tf32.tf32.f32 "
      "{%0,%1,%2,%3},{%4,%5,%6,%7},{%8,%9},{%0,%1,%2,%3};\n"
      : "+f"(c[0]), "+f"(c[1]), "+f"(c[2]), "+f"(c[3])
      : "r"(a0), "r"(a1), "r"(a2), "r"(a3), "r"(b0), "r"(b1));
}

// ---------------------------------------------------------------------------
// tf32 GEMM (NT): C[M,N] = A[M,K] * W[N,K]^T  -- exact R5 version (proven,
// ~90% of mma.sync floor). 128x128 tile, BK=32, 8 warps, warp tile 32x64.
// ---------------------------------------------------------------------------
#define GST 36
__global__ __launch_bounds__(256) void gemm_tf32_nt(
    const float* __restrict__ A, const float* __restrict__ Bw,
    float* __restrict__ C, int M, int N, int K) {
  __shared__ uint32_t As[128 * GST];
  __shared__ uint32_t Bs[128 * GST];
  int tid = threadIdx.x, lane = tid & 31, wid = tid >> 5;
  int g = lane >> 2, tg = lane & 3;
  int m0 = (wid & 3) * 32, n0 = (wid >> 2) * 64;
  int bm = blockIdx.y * 128, bn = blockIdx.x * 128;

  float c[2][8][4];
#pragma unroll
  for (int mt = 0; mt < 2; mt++)
#pragma unroll
    for (int nt = 0; nt < 8; nt++)
#pragma unroll
      for (int j = 0; j < 4; j++) c[mt][nt][j] = 0.f;

  for (int k0 = 0; k0 < K; k0 += 32) {
    float4 av[4], bv[4];
#pragma unroll
    for (int i = 0; i < 4; i++) {
      int id = tid + i * 256;
      int m = id >> 3;
      int k4 = (id & 7) << 2;
      av[i] = *(const float4*)&A[(size_t)(bm + m) * K + k0 + k4];
      bv[i] = *(const float4*)&Bw[(size_t)(bn + m) * K + k0 + k4];
    }
    __syncthreads();
#pragma unroll
    for (int i = 0; i < 4; i++) {
      int id = tid + i * 256;
      int m = id >> 3;
      int k4 = (id & 7) << 2;
      *(uint4*)&As[m * GST + k4] =
          make_uint4(f2tf(av[i].x), f2tf(av[i].y), f2tf(av[i].z), f2tf(av[i].w));
      *(uint4*)&Bs[m * GST + k4] =
          make_uint4(f2tf(bv[i].x), f2tf(bv[i].y), f2tf(bv[i].z), f2tf(bv[i].w));
    }
    __syncthreads();
#pragma unroll
    for (int kk = 0; kk < 4; kk++) {
      int k = kk * 8;
      uint32_t a[2][4];
#pragma unroll
      for (int mt = 0; mt < 2; mt++) {
        int mm = m0 + mt * 16 + g;
        a[mt][0] = As[mm * GST + k + tg];
        a[mt][1] = As[(mm + 8) * GST + k + tg];
        a[mt][2] = As[mm * GST + k + tg + 4];
        a[mt][3] = As[(mm + 8) * GST + k + tg + 4];
      }
#pragma unroll
      for (int nt = 0; nt < 8; nt++) {
        int nn = n0 + nt * 8 + g;
        uint32_t b0 = Bs[nn * GST + k + tg];
        uint32_t b1 = Bs[nn * GST + k + tg + 4];
        mma_tf32(c[0][nt], a[0][0], a[0][1], a[0][2], a[0][3], b0, b1);
        mma_tf32(c[1][nt], a[1][0], a[1][1], a[1][2], a[1][3], b0, b1);
      }
    }
  }

#pragma unroll
  for (int mt = 0; mt < 2; mt++)
#pragma unroll
    for (int nt = 0; nt < 8; nt++) {
      int row0 = bm + m0 + mt * 16 + g;
      int col = bn + n0 + nt * 8 + 2 * tg;
      *(float2*)&C[(size_t)row0 * N + col] =
          make_float2(c[mt][nt][0], c[mt][nt][1]);
      *(float2*)&C[(size_t)(row0 + 8) * N + col] =
          make_float2(c[mt][nt][2], c[mt][nt][3]);
    }
}

// ---------------------------------------------------------------------------
// Attention. Per (b,h), 64 Q-rows per block, 64-col K tiles.
// Raw fp32 in smem; cvt.rna applied to fragment registers (R5 numerics).
// ldmatrix for Q/K/Es; scalar LDS for V B-operand (natural [c][d] layout IS
// the mma B[k][n] layout -- no transpose). cp.async double-buffered K,V.
// smem words: Qs@0 (64x68), Ks@4352 (2x64x68), Vs@13056 (2x64x72),
// Es@22272 (64x68) -> 26624 words = 104KB -> 2 CTAs/SM.
// ---------------------------------------------------------------------------
#define AST 68
#define VST 72
#define QS_W 0
#define KS_W 4352
#define VS_W 13056
#define ES_W 22272
#define ATTN_SMEM (26624 * 4)

__global__ __launch_bounds__(256) void attn_kernel(
    const float* __restrict__ Pq, const float* __restrict__ Pk,
    const float* __restrict__ Pv, float* __restrict__ attn,
    float* __restrict__ ctxT) {
  extern __shared__ float smf[];
  __shared__ float lsum[64];

  int tid = threadIdx.x, lane = tid & 31, wid = tid >> 5;
  int sub = lane >> 3, l7 = lane & 7;
  int g = lane >> 2, tg = lane & 3;
  int m0 = (wid & 3) * 16, n0 = (wid >> 2) * 32;
  int qt = blockIdx.x;
  int bh = blockIdx.y;
  int b = bh >> 4, h = bh & 15;

  const float* Qb = Pq + (size_t)b * SS * DM + (size_t)h * SS * DK;
  const float* Kb = Pk + (size_t)b * SS * DM + (size_t)h * SS * DK;
  const float* Vb = Pv + (size_t)b * SS * DM + (size_t)h * SS * DK;
  float* attn_b = attn + ((size_t)bh * SS + (size_t)qt * 64) * SS;

  uint32_t sbase = su(smf);

  // ldmatrix lane base byte offsets
  uint32_t qOff =
      sbase + (QS_W + (m0 + (sub & 1) * 8 + l7) * AST + (sub >> 1) * 4) * 4;
  uint32_t eOff =
      sbase + (ES_W + (m0 + (sub & 1) * 8 + l7) * AST + (sub >> 1) * 4) * 4;
  uint32_t kOffR = ((n0 + (sub >> 1) * 8 + l7) * AST + (sub & 1) * 4) * 4;

  // cp.async chunk mapping: 1024 16B-chunks per 64x64 tile, 4 per thread
  int crow[4], ccol[4];
#pragma unroll
  for (int i = 0; i < 4; i++) {
    int cc = tid + i * 256;
    crow[i] = cc >> 4;
    ccol[i] = (cc & 15) << 2;
  }

  // prologue: Q + K0 + V0 in one group (stage 0)
#pragma unroll
  for (int i = 0; i < 4; i++) {
    cpa16(sbase + (QS_W + crow[i] * AST + ccol[i]) * 4,
          Qb + (size_t)(qt * 64 + crow[i]) * DK + ccol[i]);
    cpa16(sbase + (KS_W + crow[i] * AST + ccol[i]) * 4,
          Kb + (size_t)crow[i] * DK + ccol[i]);
    cpa16(sbase + (VS_W + crow[i] * VST + ccol[i]) * 4,
          Vb + (size_t)crow[i] * DK + ccol[i]);
  }
  cpcommit();

  if (tid < 64) lsum[tid] = 0.f;

  float o[4][4];
#pragma unroll
  for (int nt = 0; nt < 4; nt++)
#pragma unroll
    for (int j = 0; j < 4; j++) o[nt][j] = 0.f;
  float racc0 = 0.f, racc1 = 0.f;

  const int NT = SS / 64;
  for (int kt = 0; kt < NT; kt++) {
    int st = kt & 1;
    cpwait<0>();
    __syncthreads();  // K(kt),V(kt) ready; prev-iter Es/V consumers done

    // prefetch K(kt+1), V(kt+1) into other stage (overlaps whole body)
    if (kt + 1 < NT) {
#pragma unroll
      for (int i = 0; i < 4; i++) {
        cpa16(sbase +
                  (KS_W + (st ^ 1) * 4352 + crow[i] * AST + ccol[i]) * 4,
              Kb + (size_t)((kt + 1) * 64 + crow[i]) * DK + ccol[i]);
        cpa16(sbase +
                  (VS_W + (st ^ 1) * 4608 + crow[i] * VST + ccol[i]) * 4,
              Vb + (size_t)((kt + 1) * 64 + crow[i]) * DK + ccol[i]);
      }
      cpcommit();
    }

    // S = Q K^T  (warp: 16 rows x 32 cols)
    float s[4][4];
#pragma unroll
    for (int nt = 0; nt < 4; nt++)
#pragma unroll
      for (int j = 0; j < 4; j++) s[nt][j] = 0.f;
    uint32_t kBase = sbase + (KS_W + st * 4352) * 4 + kOffR;
#pragma unroll
    for (int kk = 0; kk < 8; kk++) {
      uint32_t a[4], b01[4], b23[4];
      ldsm4(a[0], a[1], a[2], a[3], qOff + kk * 32);
      ldsm4(b01[0], b01[1], b01[2], b01[3], kBase + kk * 32);
      ldsm4(b23[0], b23[1], b23[2], b23[3], kBase + 16 * AST * 4 + kk * 32);
#pragma unroll
      for (int j = 0; j < 4; j++) {
        a[j] = tfr(a[j]);
        b01[j] = tfr(b01[j]);
        b23[j] = tfr(b23[j]);
      }
      mma_tf32(s[0], a[0], a[1], a[2], a[3], b01[0], b01[1]);
      mma_tf32(s[1], a[0], a[1], a[2], a[3], b01[2], b01[3]);
      mma_tf32(s[2], a[0], a[1], a[2], a[3], b23[0], b23[1]);
      mma_tf32(s[3], a[0], a[1], a[2], a[3], b23[2], b23[3]);
    }

    // exp, write unnormalized attn, stash Es (raw fp32), row sums in regs
    int row0 = m0 + g, row1 = m0 + g + 8;
#pragma unroll
    for (int nt = 0; nt < 4; nt++) {
      float e0 = __expf(s[nt][0] * 0.125f);
      float e1 = __expf(s[nt][1] * 0.125f);
      float e2 = __expf(s[nt][2] * 0.125f);
      float e3 = __expf(s[nt][3] * 0.125f);
      racc0 += e0 + e1;
      racc1 += e2 + e3;
      int cc = n0 + nt * 8 + 2 * tg;
      *(float2*)&attn_b[(size_t)row0 * SS + kt * 64 + cc] = make_float2(e0, e1);
      *(float2*)&attn_b[(size_t)row1 * SS + kt * 64 + cc] = make_float2(e2, e3);
      *(float2*)&smf[ES_W + row0 * AST + cc] = make_float2(e0, e1);
      *(float2*)&smf[ES_W + row1 * AST + cc] = make_float2(e2, e3);
    }
    __syncthreads();  // Es visible

    // ctx += E @ V   (V natural [c][d] == B[k][n]; scalar LDS, stride-72
    // conflict-free)
    int vsBase = VS_W + st * 4608;
#pragma unroll
    for (int kk = 0; kk < 8; kk++) {
      uint32_t a[4];
      ldsm4(a[0], a[1], a[2], a[3], eOff + kk * 32);
#pragma unroll
      for (int j = 0; j < 4; j++) a[j] = tfr(a[j]);
      int kr0 = vsBase + (kk * 8 + tg) * VST;
      int kr1 = vsBase + (kk * 8 + tg + 4) * VST;
#pragma unroll
      for (int nt = 0; nt < 4; nt++) {
        int nn = n0 + nt * 8 + g;
        uint32_t b0 = f2tf(smf[kr0 + nn]);
        uint32_t b1 = f2tf(smf[kr1 + nn]);
        mma_tf32(o[nt], a[0], a[1], a[2], a[3], b0, b1);
      }
    }
  }

  // reduce row sums (each m-row covered by warps wid and wid+4)
  racc0 += __shfl_xor_sync(0xffffffffu, racc0, 1);
  racc0 += __shfl_xor_sync(0xffffffffu, racc0, 2);
  racc1 += __shfl_xor_sync(0xffffffffu, racc1, 1);
  racc1 += __shfl_xor_sync(0xffffffffu, racc1, 2);
  if (tg == 0) {
    atomicAdd(&lsum[m0 + g], racc0);
    atomicAdd(&lsum[m0 + g + 8], racc1);
  }
  __syncthreads();

  // normalize ctx, write [b, s, h*64 + d]
  {
    int row0 = m0 + g, row1 = m0 + g + 8;
    float rl0 = 1.f / lsum[row0];
    float rl1 = 1.f / lsum[row1];
#pragma unroll
    for (int nt = 0; nt < 4; nt++) {
      int col = h * DK + n0 + nt * 8 + 2 * tg;
      *(float2*)&g_ctxT[(size_t)b * SS * DM + (size_t)(qt * 64 + row0) * DM +
                        col] = make_float2(o[nt][0] * rl0, o[nt][1] * rl0);
      *(float2*)&g_ctxT[(size_t)b * SS * DM + (size_t)(qt * 64 + row1) * DM +
                        col] = make_float2(o[nt][2] * rl1, o[nt][3] * rl1);
    }
  }
  (void)ctxT;

  // rescale attn stripe in place (rows hot in L2)
  for (int idx = tid; idx < 64 * (SS / 4); idx += 256) {
    int r = idx / (SS / 4);
    int c4 = idx % (SS / 4);
    float sc = 1.f / lsum[r];
    float4* p = (float4*)&attn_b[(size_t)r * SS + c4 * 4];
    float4 vvv = *p;
    vvv.x *= sc; vvv.y *= sc; vvv.z *= sc; vvv.w *= sc;
    *p = vvv;
  }
}

// ---------------------------------------------------------------------------
// Residual add + LayerNorm, one block per row.
// ---------------------------------------------------------------------------
__global__ __launch_bounds__(256) void add_ln_kernel(
    const float* __restrict__ fc, const float* __restrict__ res,
    const float* __restrict__ gamma, const float* __restrict__ beta,
    float* __restrict__ out) {
  int row = blockIdx.x;
  int tid = threadIdx.x;
  float4 xf = ((const float4*)(fc + (size_t)row * DM))[tid];
  float4 xr = ((const float4*)(res + (size_t)row * DM))[tid];
  float x0 = xf.x + xr.x, x1 = xf.y + xr.y, x2 = xf.z + xr.z, x3 = xf.w + xr.w;
  float s = x0 + x1 + x2 + x3;
  float sq = x0 * x0 + x1 * x1 + x2 * x2 + x3 * x3;
#pragma unroll
  for (int o = 16; o; o >>= 1) {
    s += __shfl_down_sync(0xffffffffu, s, o);
    sq += __shfl_down_sync(0xffffffffu, sq, o);
  }
  __shared__ float ws[8], wq[8];
  __shared__ float mu_s, rs_s;
  if ((tid & 31) == 0) { ws[tid >> 5] = s; wq[tid >> 5] = sq; }
  __syncthreads();
  if (tid == 0) {
    float St = 0.f, Qt = 0.f;
#pragma unroll
    for (int i = 0; i < 8; i++) { St += ws[i]; Qt += wq[i]; }
    float mu = St * (1.f / DM);
    float var = Qt * (1.f / DM) - mu * mu;
    mu_s = mu;
    rs_s = rsqrtf(var + 1e-6f);
  }
  __syncthreads();
  float mu = mu_s, rs = rs_s;
  float4 g = ((const float4*)gamma)[tid];
  float4 bb = ((const float4*)beta)[tid];
  float4 o;
  o.x = (x0 - mu) * rs * g.x + bb.x;
  o.y = (x1 - mu) * rs * g.y + bb.y;
  o.z = (x2 - mu) * rs * g.z + bb.z;
  o.w = (x3 - mu) * rs * g.w + bb.w;
  ((float4*)(out + (size_t)row * DM))[tid] = o;
}

// ---------------------------------------------------------------------------
extern "C" void kernel_launch(void* const* d_in, const int* in_sizes, int n_in,
                              void* d_out, int out_size) {
  const float* q = (const float*)d_in[0];
  const float* k = (const float*)d_in[1];
  const float* v = (const float*)d_in[2];
  const float* w_qs = (const float*)d_in[3];
  const float* w_ks = (const float*)d_in[4];
  const float* w_vs = (const float*)d_in[5];
  const float* w_fc = (const float*)d_in[6];
  const float* gamma = (const float*)d_in[7];
  const float* beta = (const float*)d_in[8];
  float* out = (float*)d_out;

  const size_t out_elems = (size_t)BB * SS * DM;                // 8388608
  const size_t attn_elems = (size_t)BB * NH * SS * (size_t)SS;  // 268435456
  float* attn = ((size_t)out_size >= out_elems + attn_elems)
                    ? out + out_elems
                    : nullptr;

  float *Pq, *Pk, *Pv, *ctxT, *fcb, *attn_fb;
  cudaGetSymbolAddress((void**)&Pq, g_Pq);
  cudaGetSymbolAddress((void**)&Pk, g_Pk);
  cudaGetSymbolAddress((void**)&Pv, g_Pv);
  cudaGetSymbolAddress((void**)&ctxT, g_ctxT);
  cudaGetSymbolAddress((void**)&fcb, g_fc);
  cudaGetSymbolAddress((void**)&attn_fb, g_attn_fallback);
  if (!attn) attn = attn_fb;

  cudaFuncSetAttribute(attn_kernel,
                       cudaFuncAttributeMaxDynamicSharedMemorySize, ATTN_SMEM);

  dim3 gproj(DM / 128, (BB * SS) / 128);  // (8, 64)
  gemm_tf32_nt<<<gproj, 256>>>(q, w_qs, Pq, BB * SS, DM, DM);
  gemm_tf32_nt<<<gproj, 256>>>(k, w_ks, Pk, BB * SS, DM, DM);
  gemm_tf32_nt<<<gproj, 256>>>(v, w_vs, Pv, BB * SS, DM, DM);

  attn_kernel<<<dim3(SS / 64, BB * NH), 256, ATTN_SMEM>>>(Pq, Pk, Pv, attn,
                                                          ctxT);

  gemm_tf32_nt<<<gproj, 256>>>(ctxT, w_fc, fcb, BB * SS, DM, DM);
  add_ln_kernel<<<BB * SS, 256>>>(fcb, q, gamma, beta, out);
}

// round 10
// speedup vs baseline: 1.7112x; 1.3005x over previous
#include <cuda_runtime.h>
#include <cstdint>
#include <cstddef>

#define BB 4
#define SS 2048
#define DM 1024
#define NH 16
#define DK 64

// Scratch (allocation-free rule: __device__ globals)
__device__ float g_Pq[BB * SS * DM];
__device__ float g_Pk[BB * SS * DM];
__device__ float g_Pv[BB * SS * DM];
__device__ float g_ctxT[BB * SS * DM];
__device__ float g_fc[BB * SS * DM];
__device__ float g_attn_fallback[(size_t)BB * NH * SS * SS];

__device__ __forceinline__ uint32_t f2tf(float x) {
  uint32_t u;
  asm("cvt.rna.tf32.f32 %0, %1;" : "=r"(u) : "f"(x));
  return u;
}
__device__ __forceinline__ uint32_t su(const void* p) {
  return (uint32_t)__cvta_generic_to_shared(p);
}
__device__ __forceinline__ void cpa16(uint32_t s, const void* g) {
  asm volatile("cp.async.cg.shared.global [%0], [%1], 16;\n" ::"r"(s), "l"(g));
}
__device__ __forceinline__ void cpcommit() {
  asm volatile("cp.async.commit_group;\n");
}
template <int N>
__device__ __forceinline__ void cpwait() {
  asm volatile("cp.async.wait_group %0;\n" ::"n"(N));
}
__device__ __forceinline__ void ldsm4(uint32_t& r0, uint32_t& r1, uint32_t& r2,
                                      uint32_t& r3, uint32_t a) {
  asm volatile(
      "ldmatrix.sync.aligned.m8n8.x4.shared.b16 {%0,%1,%2,%3},[%4];\n"
      : "=r"(r0), "=r"(r1), "=r"(r2), "=r"(r3)
      : "r"(a));
}
__device__ __forceinline__ void mma_tf32(float* c, uint32_t a0, uint32_t a1,
                                         uint32_t a2, uint32_t a3, uint32_t b0,
                                         uint32_t b1) {
  asm volatile(
      "mma.sync.aligned.m16n8k8.row.col.f32.tf32.tf32.f32 "
      "{%0,%1,%2,%3},{%4,%5,%6,%7},{%8,%9},{%0,%1,%2,%3};\n"
      : "+f"(c[0]), "+f"(c[1]), "+f"(c[2]), "+f"(c[3])
      : "r"(a0), "r"(a1), "r"(a2), "r"(a3), "r"(b0), "r"(b1));
}

// ---------------------------------------------------------------------------
// tf32 GEMM (NT): C[M,N] = A[M,K] * W[N,K]^T  -- proven R5 kernel.
// RND: round output to tf32 (RNA) in the epilogue -- used for the QKV
// projections so the attention kernel can consume raw bits with no cvt.
// ---------------------------------------------------------------------------
#define GST 36
template <bool RND>
__global__ __launch_bounds__(256) void gemm_tf32_nt(
    const float* __restrict__ A, const float* __restrict__ Bw,
    float* __restrict__ C, int M, int N, int K) {
  __shared__ uint32_t As[128 * GST];
  __shared__ uint32_t Bs[128 * GST];
  int tid = threadIdx.x, lane = tid & 31, wid = tid >> 5;
  int g = lane >> 2, tg = lane & 3;
  int m0 = (wid & 3) * 32, n0 = (wid >> 2) * 64;
  int bm = blockIdx.y * 128, bn = blockIdx.x * 128;

  float c[2][8][4];
#pragma unroll
  for (int mt = 0; mt < 2; mt++)
#pragma unroll
    for (int nt = 0; nt < 8; nt++)
#pragma unroll
      for (int j = 0; j < 4; j++) c[mt][nt][j] = 0.f;

  for (int k0 = 0; k0 < K; k0 += 32) {
    float4 av[4], bv[4];
#pragma unroll
    for (int i = 0; i < 4; i++) {
      int id = tid + i * 256;
      int m = id >> 3;
      int k4 = (id & 7) << 2;
      av[i] = *(const float4*)&A[(size_t)(bm + m) * K + k0 + k4];
      bv[i] = *(const float4*)&Bw[(size_t)(bn + m) * K + k0 + k4];
    }
    __syncthreads();
#pragma unroll
    for (int i = 0; i < 4; i++) {
      int id = tid + i * 256;
      int m = id >> 3;
      int k4 = (id & 7) << 2;
      *(uint4*)&As[m * GST + k4] =
          make_uint4(f2tf(av[i].x), f2tf(av[i].y), f2tf(av[i].z), f2tf(av[i].w));
      *(uint4*)&Bs[m * GST + k4] =
          make_uint4(f2tf(bv[i].x), f2tf(bv[i].y), f2tf(bv[i].z), f2tf(bv[i].w));
    }
    __syncthreads();
#pragma unroll
    for (int kk = 0; kk < 4; kk++) {
      int k = kk * 8;
      uint32_t a[2][4];
#pragma unroll
      for (int mt = 0; mt < 2; mt++) {
        int mm = m0 + mt * 16 + g;
        a[mt][0] = As[mm * GST + k + tg];
        a[mt][1] = As[(mm + 8) * GST + k + tg];
        a[mt][2] = As[mm * GST + k + tg + 4];
        a[mt][3] = As[(mm + 8) * GST + k + tg + 4];
      }
#pragma unroll
      for (int nt = 0; nt < 8; nt++) {
        int nn = n0 + nt * 8 + g;
        uint32_t b0 = Bs[nn * GST + k + tg];
        uint32_t b1 = Bs[nn * GST + k + tg + 4];
        mma_tf32(c[0][nt], a[0][0], a[0][1], a[0][2], a[0][3], b0, b1);
        mma_tf32(c[1][nt], a[1][0], a[1][1], a[1][2], a[1][3], b0, b1);
      }
    }
  }

#pragma unroll
  for (int mt = 0; mt < 2; mt++)
#pragma unroll
    for (int nt = 0; nt < 8; nt++) {
      int row0 = bm + m0 + mt * 16 + g;
      int col = bn + n0 + nt * 8 + 2 * tg;
      float v0 = c[mt][nt][0], v1 = c[mt][nt][1];
      float v2 = c[mt][nt][2], v3 = c[mt][nt][3];
      if (RND) {
        v0 = __uint_as_float(f2tf(v0));
        v1 = __uint_as_float(f2tf(v1));
        v2 = __uint_as_float(f2tf(v2));
        v3 = __uint_as_float(f2tf(v3));
      }
      *(float2*)&C[(size_t)row0 * N + col] = make_float2(v0, v1);
      *(float2*)&C[(size_t)(row0 + 8) * N + col] = make_float2(v2, v3);
    }
}

// ---------------------------------------------------------------------------
// Attention. Per (b,h): 128 Q-rows per block, 8 warps, each warp owns
// 16 Q-rows x ALL 64 K-cols -> the PV A-fragment comes from the warp's own
// QK output via intra-quad shuffles (no Es smem, no cross-warp dependency,
// 1 sync per tile). Pq/Pk/Pv are pre-rounded to tf32 -> zero cvt on Q/K/V.
// Rowsums & normalization fully in registers (warp-private rows).
// smem: Qs@0 (128x68), Ks@8704 (2x64x68), Vs@17408 (2x64x72) = 104KB.
// ---------------------------------------------------------------------------
#define AST 68
#define VST 72
#define QS_W 0
#define KS_W 8704
#define KS_STG 4352
#define VS_W 17408
#define VS_STG 4608
#define ATTN_SMEM (26624 * 4)

__global__ __launch_bounds__(256, 2) void attn_kernel(
    const float* __restrict__ Pq, const float* __restrict__ Pk,
    const float* __restrict__ Pv, float* __restrict__ attn,
    float* __restrict__ ctxT) {
  extern __shared__ float smf[];

  int tid = threadIdx.x, lane = tid & 31, wid = tid >> 5;
  int sub = lane >> 3, l7 = lane & 7;
  int g = lane >> 2, tg = lane & 3;
  int m0 = wid * 16;  // warp's 16 Q-rows (block-local)
  int qt = blockIdx.x;  // 0..15 (128-row Q tiles)
  int bh = blockIdx.y;
  int b = bh >> 4, h = bh & 15;

  const float* Qb = Pq + (size_t)b * SS * DM + (size_t)h * SS * DK;
  const float* Kb = Pk + (size_t)b * SS * DM + (size_t)h * SS * DK;
  const float* Vb = Pv + (size_t)b * SS * DM + (size_t)h * SS * DK;
  float* attn_b = attn + ((size_t)bh * SS + (size_t)qt * 128) * SS;

  uint32_t sbase = su(smf);

  // ldmatrix lane base byte offsets
  uint32_t qOff =
      sbase + (QS_W + (m0 + (sub & 1) * 8 + l7) * AST + (sub >> 1) * 4) * 4;
  uint32_t kLane = (((sub >> 1) * 8 + l7) * AST + (sub & 1) * 4) * 4;

  // cp.async chunk maps
  int qrow[8], qcol[8];
#pragma unroll
  for (int i = 0; i < 8; i++) {  // Q: 128 rows x 16 chunks
    int cc = tid + i * 256;
    qrow[i] = cc >> 4;
    qcol[i] = (cc & 15) << 2;
  }
  int crow[4], ccol[4];
#pragma unroll
  for (int i = 0; i < 4; i++) {  // K/V: 64 rows x 16 chunks
    int cc = tid + i * 256;
    crow[i] = cc >> 4;
    ccol[i] = (cc & 15) << 2;
  }

  // prologue: Q + K0 + V0 (one group)
#pragma unroll
  for (int i = 0; i < 8; i++)
    cpa16(sbase + (QS_W + qrow[i] * AST + qcol[i]) * 4,
          Qb + (size_t)(qt * 128 + qrow[i]) * DK + qcol[i]);
#pragma unroll
  for (int i = 0; i < 4; i++) {
    cpa16(sbase + (KS_W + crow[i] * AST + ccol[i]) * 4,
          Kb + (size_t)crow[i] * DK + ccol[i]);
    cpa16(sbase + (VS_W + crow[i] * VST + ccol[i]) * 4,
          Vb + (size_t)crow[i] * DK + ccol[i]);
  }
  cpcommit();

  float o[8][4];
#pragma unroll
  for (int nt = 0; nt < 8; nt++)
#pragma unroll
    for (int j = 0; j < 4; j++) o[nt][j] = 0.f;
  float racc0 = 0.f, racc1 = 0.f;

  const int NT = SS / 64;
  for (int kt = 0; kt < NT; kt++) {
    int st = kt & 1;
    cpwait<0>();
    __syncthreads();  // stage st ready; everyone done reading st^1

    // prefetch K(kt+1), V(kt+1) into st^1 (overlaps whole tile body)
    if (kt + 1 < NT) {
#pragma unroll
      for (int i = 0; i < 4; i++) {
        cpa16(sbase + (KS_W + (st ^ 1) * KS_STG + crow[i] * AST + ccol[i]) * 4,
              Kb + (size_t)((kt + 1) * 64 + crow[i]) * DK + ccol[i]);
        cpa16(sbase + (VS_W + (st ^ 1) * VS_STG + crow[i] * VST + ccol[i]) * 4,
              Vb + (size_t)((kt + 1) * 64 + crow[i]) * DK + ccol[i]);
      }
      cpcommit();
    }

    // S = Q K^T  (warp: 16 rows x 64 cols; operands pre-rounded, no cvt)
    float s[8][4];
#pragma unroll
    for (int nt = 0; nt < 8; nt++)
#pragma unroll
      for (int j = 0; j < 4; j++) s[nt][j] = 0.f;
    uint32_t kBase = sbase + (KS_W + st * KS_STG) * 4 + kLane;
#pragma unroll
    for (int kk = 0; kk < 8; kk++) {
      uint32_t qa[4];
      ldsm4(qa[0], qa[1], qa[2], qa[3], qOff + kk * 32);
#pragma unroll
      for (int p = 0; p < 4; p++) {
        uint32_t kb[4];
        ldsm4(kb[0], kb[1], kb[2], kb[3],
              kBase + p * 16 * AST * 4 + kk * 32);
        mma_tf32(s[2 * p], qa[0], qa[1], qa[2], qa[3], kb[0], kb[1]);
        mma_tf32(s[2 * p + 1], qa[0], qa[1], qa[2], qa[3], kb[2], kb[3]);
      }
    }

    // exp -> unnormalized attn gmem + tf32 regs; rowsums in registers
    uint32_t et[8][4];
    int row0 = m0 + g, row1 = m0 + g + 8;
#pragma unroll
    for (int nt = 0; nt < 8; nt++) {
      float e0 = __expf(s[nt][0] * 0.125f);
      float e1 = __expf(s[nt][1] * 0.125f);
      float e2 = __expf(s[nt][2] * 0.125f);
      float e3 = __expf(s[nt][3] * 0.125f);
      racc0 += e0 + e1;
      racc1 += e2 + e3;
      int cc = nt * 8 + 2 * tg;
      *(float2*)&attn_b[(size_t)row0 * SS + kt * 64 + cc] = make_float2(e0, e1);
      *(float2*)&attn_b[(size_t)row1 * SS + kt * 64 + cc] = make_float2(e2, e3);
      et[nt][0] = f2tf(e0);
      et[nt][1] = f2tf(e1);
      et[nt][2] = f2tf(e2);
      et[nt][3] = f2tf(e3);
    }

    // ctx += E @ V : A-fragments from et via intra-quad shuffles,
    // B from Vs natural [c][d] layout (pre-rounded, no cvt).
    int vsBase = VS_W + st * VS_STG;
#pragma unroll
    for (int kk = 0; kk < 8; kk++) {
      int qlo = tg >> 1, qhi = (tg >> 1) + 2;
      uint32_t lo0 = __shfl_sync(0xffffffffu, et[kk][0], qlo, 4);
      uint32_t lo1 = __shfl_sync(0xffffffffu, et[kk][1], qlo, 4);
      uint32_t lo2 = __shfl_sync(0xffffffffu, et[kk][2], qlo, 4);
      uint32_t lo3 = __shfl_sync(0xffffffffu, et[kk][3], qlo, 4);
      uint32_t hi0 = __shfl_sync(0xffffffffu, et[kk][0], qhi, 4);
      uint32_t hi1 = __shfl_sync(0xffffffffu, et[kk][1], qhi, 4);
      uint32_t hi2 = __shfl_sync(0xffffffffu, et[kk][2], qhi, 4);
      uint32_t hi3 = __shfl_sync(0xffffffffu, et[kk][3], qhi, 4);
      uint32_t a0 = (tg & 1) ? lo1 : lo0;  // E[g][8kk+tg]
      uint32_t a1 = (tg & 1) ? lo3 : lo2;  // E[g+8][8kk+tg]
      uint32_t a2 = (tg & 1) ? hi1 : hi0;  // E[g][8kk+tg+4]
      uint32_t a3 = (tg & 1) ? hi3 : hi2;  // E[g+8][8kk+tg+4]
      int kr0 = vsBase + (kk * 8 + tg) * VST;
      int kr1 = vsBase + (kk * 8 + tg + 4) * VST;
#pragma unroll
      for (int nt = 0; nt < 8; nt++) {
        uint32_t b0 = __float_as_uint(smf[kr0 + nt * 8 + g]);
        uint32_t b1 = __float_as_uint(smf[kr1 + nt * 8 + g]);
        mma_tf32(o[nt], a0, a1, a2, a3, b0, b1);
      }
    }
  }

  // quad-reduce rowsums (rows are warp-private)
  racc0 += __shfl_xor_sync(0xffffffffu, racc0, 1);
  racc0 += __shfl_xor_sync(0xffffffffu, racc0, 2);
  racc1 += __shfl_xor_sync(0xffffffffu, racc1, 1);
  racc1 += __shfl_xor_sync(0xffffffffu, racc1, 2);
  float rl0 = 1.f / racc0, rl1 = 1.f / racc1;

  // normalize ctx, write [b, s, h*64 + d]
  {
    int row0 = qt * 128 + m0 + g, row1 = row0 + 8;
#pragma unroll
    for (int nt = 0; nt < 8; nt++) {
      int col = h * DK + nt * 8 + 2 * tg;
      *(float2*)&g_ctxT[(size_t)b * SS * DM + (size_t)row0 * DM + col] =
          make_float2(o[nt][0] * rl0, o[nt][1] * rl0);
      *(float2*)&g_ctxT[(size_t)b * SS * DM + (size_t)row1 * DM + col] =
          make_float2(o[nt][2] * rl1, o[nt][3] * rl1);
    }
  }
  (void)ctxT;

  // rescale this warp's 16 attn rows in place (rows hot in L2)
  __syncwarp();
#pragma unroll 1
  for (int rr = 0; rr < 16; rr++) {
    float rl = __shfl_sync(0xffffffffu, rr < 8 ? rl0 : rl1, (rr & 7) << 2);
    float* rowp = attn_b + (size_t)(m0 + rr) * SS;
    for (int c = lane * 4; c < SS; c += 128) {
      float4* p = (float4*)&rowp[c];
      float4 vv = *p;
      vv.x *= rl; vv.y *= rl; vv.z *= rl; vv.w *= rl;
      *p = vv;
    }
  }
}

// ---------------------------------------------------------------------------
// Residual add + LayerNorm, one block per row.
// ---------------------------------------------------------------------------
__global__ __launch_bounds__(256) void add_ln_kernel(
    const float* __restrict__ fc, const float* __restrict__ res,
    const float* __restrict__ gamma, const float* __restrict__ beta,
    float* __restrict__ out) {
  int row = blockIdx.x;
  int tid = threadIdx.x;
  float4 xf = ((const float4*)(fc + (size_t)row * DM))[tid];
  float4 xr = ((const float4*)(res + (size_t)row * DM))[tid];
  float x0 = xf.x + xr.x, x1 = xf.y + xr.y, x2 = xf.z + xr.z, x3 = xf.w + xr.w;
  float s = x0 + x1 + x2 + x3;
  float sq = x0 * x0 + x1 * x1 + x2 * x2 + x3 * x3;
#pragma unroll
  for (int o = 16; o; o >>= 1) {
    s += __shfl_down_sync(0xffffffffu, s, o);
    sq += __shfl_down_sync(0xffffffffu, sq, o);
  }
  __shared__ float ws[8], wq[8];
  __shared__ float mu_s, rs_s;
  if ((tid & 31) == 0) { ws[tid >> 5] = s; wq[tid >> 5] = sq; }
  __syncthreads();
  if (tid == 0) {
    float St = 0.f, Qt = 0.f;
#pragma unroll
    for (int i = 0; i < 8; i++) { St += ws[i]; Qt += wq[i]; }
    float mu = St * (1.f / DM);
    float var = Qt * (1.f / DM) - mu * mu;
    mu_s = mu;
    rs_s = rsqrtf(var + 1e-6f);
  }
  __syncthreads();
  float mu = mu_s, rs = rs_s;
  float4 g = ((const float4*)gamma)[tid];
  float4 bb = ((const float4*)beta)[tid];
  float4 o;
  o.x = (x0 - mu) * rs * g.x + bb.x;
  o.y = (x1 - mu) * rs * g.y + bb.y;
  o.z = (x2 - mu) * rs * g.z + bb.z;
  o.w = (x3 - mu) * rs * g.w + bb.w;
  ((float4*)(out + (size_t)row * DM))[tid] = o;
}

// ---------------------------------------------------------------------------
extern "C" void kernel_launch(void* const* d_in, const int* in_sizes, int n_in,
                              void* d_out, int out_size) {
  const float* q = (const float*)d_in[0];
  const float* k = (const float*)d_in[1];
  const float* v = (const float*)d_in[2];
  const float* w_qs = (const float*)d_in[3];
  const float* w_ks = (const float*)d_in[4];
  const float* w_vs = (const float*)d_in[5];
  const float* w_fc = (const float*)d_in[6];
  const float* gamma = (const float*)d_in[7];
  const float* beta = (const float*)d_in[8];
  float* out = (float*)d_out;

  const size_t out_elems = (size_t)BB * SS * DM;                // 8388608
  const size_t attn_elems = (size_t)BB * NH * SS * (size_t)SS;  // 268435456
  float* attn = ((size_t)out_size >= out_elems + attn_elems)
                    ? out + out_elems
                    : nullptr;

  float *Pq, *Pk, *Pv, *ctxT, *fcb, *attn_fb;
  cudaGetSymbolAddress((void**)&Pq, g_Pq);
  cudaGetSymbolAddress((void**)&Pk, g_Pk);
  cudaGetSymbolAddress((void**)&Pv, g_Pv);
  cudaGetSymbolAddress((void**)&ctxT, g_ctxT);
  cudaGetSymbolAddress((void**)&fcb, g_fc);
  cudaGetSymbolAddress((void**)&attn_fb, g_attn_fallback);
  if (!attn) attn = attn_fb;

  cudaFuncSetAttribute(attn_kernel,
                       cudaFuncAttributeMaxDynamicSharedMemorySize, ATTN_SMEM);

  dim3 gproj(DM / 128, (BB * SS) / 128);  // (8, 64)
  gemm_tf32_nt<true><<<gproj, 256>>>(q, w_qs, Pq, BB * SS, DM, DM);
  gemm_tf32_nt<true><<<gproj, 256>>>(k, w_ks, Pk, BB * SS, DM, DM);
  gemm_tf32_nt<true><<<gproj, 256>>>(v, w_vs, Pv, BB * SS, DM, DM);

  attn_kernel<<<dim3(SS / 128, BB * NH), 256, ATTN_SMEM>>>(Pq, Pk, Pv, attn,
                                                           ctxT);

  gemm_tf32_nt<false><<<gproj, 256>>>(ctxT, w_fc, fcb, BB * SS, DM, DM);
  add_ln_kernel<<<BB * SS, 256>>>(fcb, q, gamma, beta, out);
}

// round 11
// speedup vs baseline: 1.7923x; 1.0474x over previous
#include <cuda_runtime.h>
#include <cstdint>
#include <cstddef>

#define BB 4
#define SS 2048
#define DM 1024
#define NH 16
#define DK 64

// Scratch (allocation-free rule: __device__ globals)
__device__ float g_Pq[BB * SS * DM];
__device__ float g_Pk[BB * SS * DM];
__device__ float g_Pv[BB * SS * DM];
__device__ float g_ctxT[BB * SS * DM];
__device__ float g_fc[BB * SS * DM];
__device__ float g_attn_fallback[(size_t)BB * NH * SS * SS];

__device__ __forceinline__ uint32_t f2tf(float x) {
  uint32_t u;
  asm("cvt.rna.tf32.f32 %0, %1;" : "=r"(u) : "f"(x));
  return u;
}
__device__ __forceinline__ uint32_t su(const void* p) {
  return (uint32_t)__cvta_generic_to_shared(p);
}
__device__ __forceinline__ void cpa16(uint32_t s, const void* g) {
  asm volatile("cp.async.cg.shared.global [%0], [%1], 16;\n" ::"r"(s), "l"(g));
}
__device__ __forceinline__ void cpcommit() {
  asm volatile("cp.async.commit_group;\n");
}
template <int N>
__device__ __forceinline__ void cpwait() {
  asm volatile("cp.async.wait_group %0;\n" ::"n"(N));
}
__device__ __forceinline__ void ldsm4(uint32_t& r0, uint32_t& r1, uint32_t& r2,
                                      uint32_t& r3, uint32_t a) {
  asm volatile(
      "ldmatrix.sync.aligned.m8n8.x4.shared.b16 {%0,%1,%2,%3},[%4];\n"
      : "=r"(r0), "=r"(r1), "=r"(r2), "=r"(r3)
      : "r"(a));
}
__device__ __forceinline__ void mma_tf32(float* c, uint32_t a0, uint32_t a1,
                                         uint32_t a2, uint32_t a3, uint32_t b0,
                                         uint32_t b1) {
  asm volatile(
      "mma.sync.aligned.m16n8k8.row.col.f32.tf32.tf32.f32 "
      "{%0,%1,%2,%3},{%4,%5,%6,%7},{%8,%9},{%0,%1,%2,%3};\n"
      : "+f"(c[0]), "+f"(c[1]), "+f"(c[2]), "+f"(c[3])
      : "r"(a0), "r"(a1), "r"(a2), "r"(a3), "r"(b0), "r"(b1));
}

// ---------------------------------------------------------------------------
// tf32 GEMM (NT): C[M,N] = A[M,K] * W[N,K]^T  -- proven R5 kernel.
// RND: round output to tf32 (RNA) in the epilogue -- used for the QKV
// projections so the attention kernel can consume raw bits with no cvt.
// ---------------------------------------------------------------------------
#define GST 36
template <bool RND>
__global__ __launch_bounds__(256) void gemm_tf32_nt(
    const float* __restrict__ A, const float* __restrict__ Bw,
    float* __restrict__ C, int M, int N, int K) {
  __shared__ uint32_t As[128 * GST];
  __shared__ uint32_t Bs[128 * GST];
  int tid = threadIdx.x, lane = tid & 31, wid = tid >> 5;
  int g = lane >> 2, tg = lane & 3;
  int m0 = (wid & 3) * 32, n0 = (wid >> 2) * 64;
  int bm = blockIdx.y * 128, bn = blockIdx.x * 128;

  float c[2][8][4];
#pragma unroll
  for (int mt = 0; mt < 2; mt++)
#pragma unroll
    for (int nt = 0; nt < 8; nt++)
#pragma unroll
      for (int j = 0; j < 4; j++) c[mt][nt][j] = 0.f;

  for (int k0 = 0; k0 < K; k0 += 32) {
    float4 av[4], bv[4];
#pragma unroll
    for (int i = 0; i < 4; i++) {
      int id = tid + i * 256;
      int m = id >> 3;
      int k4 = (id & 7) << 2;
      av[i] = *(const float4*)&A[(size_t)(bm + m) * K + k0 + k4];
      bv[i] = *(const float4*)&Bw[(size_t)(bn + m) * K + k0 + k4];
    }
    __syncthreads();
#pragma unroll
    for (int i = 0; i < 4; i++) {
      int id = tid + i * 256;
      int m = id >> 3;
      int k4 = (id & 7) << 2;
      *(uint4*)&As[m * GST + k4] =
          make_uint4(f2tf(av[i].x), f2tf(av[i].y), f2tf(av[i].z), f2tf(av[i].w));
      *(uint4*)&Bs[m * GST + k4] =
          make_uint4(f2tf(bv[i].x), f2tf(bv[i].y), f2tf(bv[i].z), f2tf(bv[i].w));
    }
    __syncthreads();
#pragma unroll
    for (int kk = 0; kk < 4; kk++) {
      int k = kk * 8;
      uint32_t a[2][4];
#pragma unroll
      for (int mt = 0; mt < 2; mt++) {
        int mm = m0 + mt * 16 + g;
        a[mt][0] = As[mm * GST + k + tg];
        a[mt][1] = As[(mm + 8) * GST + k + tg];
        a[mt][2] = As[mm * GST + k + tg + 4];
        a[mt][3] = As[(mm + 8) * GST + k + tg + 4];
      }
#pragma unroll
      for (int nt = 0; nt < 8; nt++) {
        int nn = n0 + nt * 8 + g;
        uint32_t b0 = Bs[nn * GST + k + tg];
        uint32_t b1 = Bs[nn * GST + k + tg + 4];
        mma_tf32(c[0][nt], a[0][0], a[0][1], a[0][2], a[0][3], b0, b1);
        mma_tf32(c[1][nt], a[1][0], a[1][1], a[1][2], a[1][3], b0, b1);
      }
    }
  }

#pragma unroll
  for (int mt = 0; mt < 2; mt++)
#pragma unroll
    for (int nt = 0; nt < 8; nt++) {
      int row0 = bm + m0 + mt * 16 + g;
      int col = bn + n0 + nt * 8 + 2 * tg;
      float v0 = c[mt][nt][0], v1 = c[mt][nt][1];
      float v2 = c[mt][nt][2], v3 = c[mt][nt][3];
      if (RND) {
        v0 = __uint_as_float(f2tf(v0));
        v1 = __uint_as_float(f2tf(v1));
        v2 = __uint_as_float(f2tf(v2));
        v3 = __uint_as_float(f2tf(v3));
      }
      *(float2*)&C[(size_t)row0 * N + col] = make_float2(v0, v1);
      *(float2*)&C[(size_t)(row0 + 8) * N + col] = make_float2(v2, v3);
    }
}

// ---------------------------------------------------------------------------
// Attention, two-pass normalization (no 2.1GB rescale round-trip):
//  Pass A: per K-tile QK-mma -> exp -> rowsum + PV accumulate. NO attn write.
//  Then: quad-reduce rowsums, normalize ctx, write ctxT.
//  Pass B: QK-mma again (Qs persists; K re-streamed), exp, scale by 1/rowsum,
//  single normalized streaming write (__stcs; attn is never re-read).
// Pass B's S is bitwise-identical to pass A's -> rows sum to 1 exactly.
// Per (b,h): 128 Q-rows/block, 8 warps, warp owns 16 rows x all 64 cols;
// PV A-fragment from own QK output via intra-quad shuffles.
// smem: Qs@0 (128x68), Ks@8704 (2x64x68), Vs@17408 (2x64x72) = 104KB.
// ---------------------------------------------------------------------------
#define AST 68
#define VST 72
#define QS_W 0
#define KS_W 8704
#define KS_STG 4352
#define VS_W 17408
#define VS_STG 4608
#define ATTN_SMEM (26624 * 4)

__global__ __launch_bounds__(256, 2) void attn_kernel(
    const float* __restrict__ Pq, const float* __restrict__ Pk,
    const float* __restrict__ Pv, float* __restrict__ attn,
    float* __restrict__ ctxT) {
  extern __shared__ float smf[];

  int tid = threadIdx.x, lane = tid & 31, wid = tid >> 5;
  int sub = lane >> 3, l7 = lane & 7;
  int g = lane >> 2, tg = lane & 3;
  int m0 = wid * 16;    // warp's 16 Q-rows (block-local)
  int qt = blockIdx.x;  // 0..15 (128-row Q tiles)
  int bh = blockIdx.y;
  int b = bh >> 4, h = bh & 15;

  const float* Qb = Pq + (size_t)b * SS * DM + (size_t)h * SS * DK;
  const float* Kb = Pk + (size_t)b * SS * DM + (size_t)h * SS * DK;
  const float* Vb = Pv + (size_t)b * SS * DM + (size_t)h * SS * DK;
  float* attn_b = attn + ((size_t)bh * SS + (size_t)qt * 128) * SS;

  uint32_t sbase = su(smf);

  // ldmatrix lane base byte offsets
  uint32_t qOff =
      sbase + (QS_W + (m0 + (sub & 1) * 8 + l7) * AST + (sub >> 1) * 4) * 4;
  uint32_t kLane = (((sub >> 1) * 8 + l7) * AST + (sub & 1) * 4) * 4;

  // cp.async chunk maps
  int qrow[8], qcol[8];
#pragma unroll
  for (int i = 0; i < 8; i++) {  // Q: 128 rows x 16 chunks
    int cc = tid + i * 256;
    qrow[i] = cc >> 4;
    qcol[i] = (cc & 15) << 2;
  }
  int crow[4], ccol[4];
#pragma unroll
  for (int i = 0; i < 4; i++) {  // K/V: 64 rows x 16 chunks
    int cc = tid + i * 256;
    crow[i] = cc >> 4;
    ccol[i] = (cc & 15) << 2;
  }

  // prologue: Q + K0 + V0 (one group)
#pragma unroll
  for (int i = 0; i < 8; i++)
    cpa16(sbase + (QS_W + qrow[i] * AST + qcol[i]) * 4,
          Qb + (size_t)(qt * 128 + qrow[i]) * DK + qcol[i]);
#pragma unroll
  for (int i = 0; i < 4; i++) {
    cpa16(sbase + (KS_W + crow[i] * AST + ccol[i]) * 4,
          Kb + (size_t)crow[i] * DK + ccol[i]);
    cpa16(sbase + (VS_W + crow[i] * VST + ccol[i]) * 4,
          Vb + (size_t)crow[i] * DK + ccol[i]);
  }
  cpcommit();

  float o[8][4];
#pragma unroll
  for (int nt = 0; nt < 8; nt++)
#pragma unroll
    for (int j = 0; j < 4; j++) o[nt][j] = 0.f;
  float racc0 = 0.f, racc1 = 0.f;

  const int NT = SS / 64;

  // ================= Pass A: rowsums + PV (no attn write) =================
  for (int kt = 0; kt < NT; kt++) {
    int st = kt & 1;
    cpwait<0>();
    __syncthreads();  // stage st ready; everyone done reading st^1

    if (kt + 1 < NT) {
#pragma unroll
      for (int i = 0; i < 4; i++) {
        cpa16(sbase + (KS_W + (st ^ 1) * KS_STG + crow[i] * AST + ccol[i]) * 4,
              Kb + (size_t)((kt + 1) * 64 + crow[i]) * DK + ccol[i]);
        cpa16(sbase + (VS_W + (st ^ 1) * VS_STG + crow[i] * VST + ccol[i]) * 4,
              Vb + (size_t)((kt + 1) * 64 + crow[i]) * DK + ccol[i]);
      }
      cpcommit();
    }

    // S = Q K^T  (warp: 16 rows x 64 cols; operands pre-rounded, no cvt)
    float s[8][4];
#pragma unroll
    for (int nt = 0; nt < 8; nt++)
#pragma unroll
      for (int j = 0; j < 4; j++) s[nt][j] = 0.f;
    uint32_t kBase = sbase + (KS_W + st * KS_STG) * 4 + kLane;
#pragma unroll
    for (int kk = 0; kk < 8; kk++) {
      uint32_t qa[4];
      ldsm4(qa[0], qa[1], qa[2], qa[3], qOff + kk * 32);
#pragma unroll
      for (int p = 0; p < 4; p++) {
        uint32_t kb[4];
        ldsm4(kb[0], kb[1], kb[2], kb[3], kBase + p * 16 * AST * 4 + kk * 32);
        mma_tf32(s[2 * p], qa[0], qa[1], qa[2], qa[3], kb[0], kb[1]);
        mma_tf32(s[2 * p + 1], qa[0], qa[1], qa[2], qa[3], kb[2], kb[3]);
      }
    }

    // exp -> tf32 regs; rowsums in registers (NO gmem write in pass A)
    uint32_t et[8][4];
#pragma unroll
    for (int nt = 0; nt < 8; nt++) {
      float e0 = __expf(s[nt][0] * 0.125f);
      float e1 = __expf(s[nt][1] * 0.125f);
      float e2 = __expf(s[nt][2] * 0.125f);
      float e3 = __expf(s[nt][3] * 0.125f);
      racc0 += e0 + e1;
      racc1 += e2 + e3;
      et[nt][0] = f2tf(e0);
      et[nt][1] = f2tf(e1);
      et[nt][2] = f2tf(e2);
      et[nt][3] = f2tf(e3);
    }

    // ctx += E @ V : A-fragments from et via intra-quad shuffles,
    // B from Vs natural [c][d] layout (pre-rounded, no cvt).
    int vsBase = VS_W + st * VS_STG;
#pragma unroll
    for (int kk = 0; kk < 8; kk++) {
      int qlo = tg >> 1, qhi = (tg >> 1) + 2;
      uint32_t lo0 = __shfl_sync(0xffffffffu, et[kk][0], qlo, 4);
      uint32_t lo1 = __shfl_sync(0xffffffffu, et[kk][1], qlo, 4);
      uint32_t lo2 = __shfl_sync(0xffffffffu, et[kk][2], qlo, 4);
      uint32_t lo3 = __shfl_sync(0xffffffffu, et[kk][3], qlo, 4);
      uint32_t hi0 = __shfl_sync(0xffffffffu, et[kk][0], qhi, 4);
      uint32_t hi1 = __shfl_sync(0xffffffffu, et[kk][1], qhi, 4);
      uint32_t hi2 = __shfl_sync(0xffffffffu, et[kk][2], qhi, 4);
      uint32_t hi3 = __shfl_sync(0xffffffffu, et[kk][3], qhi, 4);
      uint32_t a0 = (tg & 1) ? lo1 : lo0;  // E[g][8kk+tg]
      uint32_t a1 = (tg & 1) ? lo3 : lo2;  // E[g+8][8kk+tg]
      uint32_t a2 = (tg & 1) ? hi1 : hi0;  // E[g][8kk+tg+4]
      uint32_t a3 = (tg & 1) ? hi3 : hi2;  // E[g+8][8kk+tg+4]
      int kr0 = vsBase + (kk * 8 + tg) * VST;
      int kr1 = vsBase + (kk * 8 + tg + 4) * VST;
#pragma unroll
      for (int nt = 0; nt < 8; nt++) {
        uint32_t b0 = __float_as_uint(smf[kr0 + nt * 8 + g]);
        uint32_t b1 = __float_as_uint(smf[kr1 + nt * 8 + g]);
        mma_tf32(o[nt], a0, a1, a2, a3, b0, b1);
      }
    }
  }

  // quad-reduce rowsums (rows are warp-private)
  racc0 += __shfl_xor_sync(0xffffffffu, racc0, 1);
  racc0 += __shfl_xor_sync(0xffffffffu, racc0, 2);
  racc1 += __shfl_xor_sync(0xffffffffu, racc1, 1);
  racc1 += __shfl_xor_sync(0xffffffffu, racc1, 2);
  float rl0 = 1.f / racc0, rl1 = 1.f / racc1;

  // normalize ctx, write [b, s, h*64 + d]  (frees o[][] before pass B)
  {
    int row0 = qt * 128 + m0 + g, row1 = row0 + 8;
#pragma unroll
    for (int nt = 0; nt < 8; nt++) {
      int col = h * DK + nt * 8 + 2 * tg;
      *(float2*)&g_ctxT[(size_t)b * SS * DM + (size_t)row0 * DM + col] =
          make_float2(o[nt][0] * rl0, o[nt][1] * rl0);
      *(float2*)&g_ctxT[(size_t)b * SS * DM + (size_t)row1 * DM + col] =
          make_float2(o[nt][2] * rl1, o[nt][3] * rl1);
    }
  }
  (void)ctxT;

  // ======= Pass B: recompute S bitwise-identically, write normalized =======
  // prologue: K0 -> stage 0 (safe: all warps past their kt=30 stage-0 reads)
#pragma unroll
  for (int i = 0; i < 4; i++)
    cpa16(sbase + (KS_W + crow[i] * AST + ccol[i]) * 4,
          Kb + (size_t)crow[i] * DK + ccol[i]);
  cpcommit();

  for (int kt = 0; kt < NT; kt++) {
    int st = kt & 1;
    cpwait<0>();
    __syncthreads();

    if (kt + 1 < NT) {
#pragma unroll
      for (int i = 0; i < 4; i++)
        cpa16(sbase + (KS_W + (st ^ 1) * KS_STG + crow[i] * AST + ccol[i]) * 4,
              Kb + (size_t)((kt + 1) * 64 + crow[i]) * DK + ccol[i]);
      cpcommit();
    }

    float s[8][4];
#pragma unroll
    for (int nt = 0; nt < 8; nt++)
#pragma unroll
      for (int j = 0; j < 4; j++) s[nt][j] = 0.f;
    uint32_t kBase = sbase + (KS_W + st * KS_STG) * 4 + kLane;
#pragma unroll
    for (int kk = 0; kk < 8; kk++) {
      uint32_t qa[4];
      ldsm4(qa[0], qa[1], qa[2], qa[3], qOff + kk * 32);
#pragma unroll
      for (int p = 0; p < 4; p++) {
        uint32_t kb[4];
        ldsm4(kb[0], kb[1], kb[2], kb[3], kBase + p * 16 * AST * 4 + kk * 32);
        mma_tf32(s[2 * p], qa[0], qa[1], qa[2], qa[3], kb[0], kb[1]);
        mma_tf32(s[2 * p + 1], qa[0], qa[1], qa[2], qa[3], kb[2], kb[3]);
      }
    }

    int row0 = m0 + g, row1 = m0 + g + 8;
#pragma unroll
    for (int nt = 0; nt < 8; nt++) {
      float e0 = __expf(s[nt][0] * 0.125f) * rl0;
      float e1 = __expf(s[nt][1] * 0.125f) * rl0;
      float e2 = __expf(s[nt][2] * 0.125f) * rl1;
      float e3 = __expf(s[nt][3] * 0.125f) * rl1;
      int cc = nt * 8 + 2 * tg;
      __stcs((float2*)&attn_b[(size_t)row0 * SS + kt * 64 + cc],
             make_float2(e0, e1));
      __stcs((float2*)&attn_b[(size_t)row1 * SS + kt * 64 + cc],
             make_float2(e2, e3));
    }
  }
}

// ---------------------------------------------------------------------------
// Residual add + LayerNorm, one block per row.
// ---------------------------------------------------------------------------
__global__ __launch_bounds__(256) void add_ln_kernel(
    const float* __restrict__ fc, const float* __restrict__ res,
    const float* __restrict__ gamma, const float* __restrict__ beta,
    float* __restrict__ out) {
  int row = blockIdx.x;
  int tid = threadIdx.x;
  float4 xf = ((const float4*)(fc + (size_t)row * DM))[tid];
  float4 xr = ((const float4*)(res + (size_t)row * DM))[tid];
  float x0 = xf.x + xr.x, x1 = xf.y + xr.y, x2 = xf.z + xr.z, x3 = xf.w + xr.w;
  float s = x0 + x1 + x2 + x3;
  float sq = x0 * x0 + x1 * x1 + x2 * x2 + x3 * x3;
#pragma unroll
  for (int o = 16; o; o >>= 1) {
    s += __shfl_down_sync(0xffffffffu, s, o);
    sq += __shfl_down_sync(0xffffffffu, sq, o);
  }
  __shared__ float ws[8], wq[8];
  __shared__ float mu_s, rs_s;
  if ((tid & 31) == 0) { ws[tid >> 5] = s; wq[tid >> 5] = sq; }
  __syncthreads();
  if (tid == 0) {
    float St = 0.f, Qt = 0.f;
#pragma unroll
    for (int i = 0; i < 8; i++) { St += ws[i]; Qt += wq[i]; }
    float mu = St * (1.f / DM);
    float var = Qt * (1.f / DM) - mu * mu;
    mu_s = mu;
    rs_s = rsqrtf(var + 1e-6f);
  }
  __syncthreads();
  float mu = mu_s, rs = rs_s;
  float4 g = ((const float4*)gamma)[tid];
  float4 bb = ((const float4*)beta)[tid];
  float4 o;
  o.x = (x0 - mu) * rs * g.x + bb.x;
  o.y = (x1 - mu) * rs * g.y + bb.y;
  o.z = (x2 - mu) * rs * g.z + bb.z;
  o.w = (x3 - mu) * rs * g.w + bb.w;
  ((float4*)(out + (size_t)row * DM))[tid] = o;
}

// ---------------------------------------------------------------------------
extern "C" void kernel_launch(void* const* d_in, const int* in_sizes, int n_in,
                              void* d_out, int out_size) {
  const float* q = (const float*)d_in[0];
  const float* k = (const float*)d_in[1];
  const float* v = (const float*)d_in[2];
  const float* w_qs = (const float*)d_in[3];
  const float* w_ks = (const float*)d_in[4];
  const float* w_vs = (const float*)d_in[5];
  const float* w_fc = (const float*)d_in[6];
  const float* gamma = (const float*)d_in[7];
  const float* beta = (const float*)d_in[8];
  float* out = (float*)d_out;

  const size_t out_elems = (size_t)BB * SS * DM;                // 8388608
  const size_t attn_elems = (size_t)BB * NH * SS * (size_t)SS;  // 268435456
  float* attn = ((size_t)out_size >= out_elems + attn_elems)
                    ? out + out_elems
                    : nullptr;

  float *Pq, *Pk, *Pv, *ctxT, *fcb, *attn_fb;
  cudaGetSymbolAddress((void**)&Pq, g_Pq);
  cudaGetSymbolAddress((void**)&Pk, g_Pk);
  cudaGetSymbolAddress((void**)&Pv, g_Pv);
  cudaGetSymbolAddress((void**)&ctxT, g_ctxT);
  cudaGetSymbolAddress((void**)&fcb, g_fc);
  cudaGetSymbolAddress((void**)&attn_fb, g_attn_fallback);
  if (!attn) attn = attn_fb;

  cudaFuncSetAttribute(attn_kernel,
                       cudaFuncAttributeMaxDynamicSharedMemorySize, ATTN_SMEM);

  dim3 gproj(DM / 128, (BB * SS) / 128);  // (8, 64)
  gemm_tf32_nt<true><<<gproj, 256>>>(q, w_qs, Pq, BB * SS, DM, DM);
  gemm_tf32_nt<true><<<gproj, 256>>>(k, w_ks, Pk, BB * SS, DM, DM);
  gemm_tf32_nt<true><<<gproj, 256>>>(v, w_vs, Pv, BB * SS, DM, DM);

  attn_kernel<<<dim3(SS / 128, BB * NH), 256, ATTN_SMEM>>>(Pq, Pk, Pv, attn,
                                                           ctxT);

  gemm_tf32_nt<false><<<gproj, 256>>>(ctxT, w_fc, fcb, BB * SS, DM, DM);
  add_ln_kernel<<<BB * SS, 256>>>(fcb, q, gamma, beta, out);
}

// round 12
// speedup vs baseline: 1.9486x; 1.0872x over previous
#include <cuda_runtime.h>
#include <cstdint>
#include <cstddef>

#define BB 4
#define SS 2048
#define DM 1024
#define NH 16
#define DK 64

// Scratch (allocation-free rule: __device__ globals)
__device__ float g_Pq[BB * SS * DM];
__device__ float g_Pk[BB * SS * DM];
__device__ float g_Pv[BB * SS * DM];
__device__ float g_ctxT[BB * SS * DM];
__device__ float g_fc[BB * SS * DM];
__device__ float g_attn_fallback[(size_t)BB * NH * SS * SS];

__device__ __forceinline__ uint32_t f2tf(float x) {
  uint32_t u;
  asm("cvt.rna.tf32.f32 %0, %1;" : "=r"(u) : "f"(x));
  return u;
}
__device__ __forceinline__ uint32_t su(const void* p) {
  return (uint32_t)__cvta_generic_to_shared(p);
}
__device__ __forceinline__ void cpa16(uint32_t s, const void* g) {
  asm volatile("cp.async.cg.shared.global [%0], [%1], 16;\n" ::"r"(s), "l"(g));
}
__device__ __forceinline__ void cpcommit() {
  asm volatile("cp.async.commit_group;\n");
}
template <int N>
__device__ __forceinline__ void cpwait() {
  asm volatile("cp.async.wait_group %0;\n" ::"n"(N));
}
__device__ __forceinline__ void ldsm4(uint32_t& r0, uint32_t& r1, uint32_t& r2,
                                      uint32_t& r3, uint32_t a) {
  asm volatile(
      "ldmatrix.sync.aligned.m8n8.x4.shared.b16 {%0,%1,%2,%3},[%4];\n"
      : "=r"(r0), "=r"(r1), "=r"(r2), "=r"(r3)
      : "r"(a));
}
__device__ __forceinline__ void mma_tf32(float* c, uint32_t a0, uint32_t a1,
                                         uint32_t a2, uint32_t a3, uint32_t b0,
                                         uint32_t b1) {
  asm volatile(
      "mma.sync.aligned.m16n8k8.row.col.f32.tf32.tf32.f32 "
      "{%0,%1,%2,%3},{%4,%5,%6,%7},{%8,%9},{%0,%1,%2,%3};\n"
      : "+f"(c[0]), "+f"(c[1]), "+f"(c[2]), "+f"(c[3])
      : "r"(a0), "r"(a1), "r"(a2), "r"(a3), "r"(b0), "r"(b1));
}

// ---------------------------------------------------------------------------
// tf32 GEMM (NT): C[M,N] = A[M,K] * W[N,K]^T  -- proven R5 kernel.
// RND: round output to tf32 (RNA) in the epilogue -- used for the QKV
// projections so the attention kernel can consume raw bits with no cvt.
// ---------------------------------------------------------------------------
#define GST 36
template <bool RND>
__global__ __launch_bounds__(256) void gemm_tf32_nt(
    const float* __restrict__ A, const float* __restrict__ Bw,
    float* __restrict__ C, int M, int N, int K) {
  __shared__ uint32_t As[128 * GST];
  __shared__ uint32_t Bs[128 * GST];
  int tid = threadIdx.x, lane = tid & 31, wid = tid >> 5;
  int g = lane >> 2, tg = lane & 3;
  int m0 = (wid & 3) * 32, n0 = (wid >> 2) * 64;
  int bm = blockIdx.y * 128, bn = blockIdx.x * 128;

  float c[2][8][4];
#pragma unroll
  for (int mt = 0; mt < 2; mt++)
#pragma unroll
    for (int nt = 0; nt < 8; nt++)
#pragma unroll
      for (int j = 0; j < 4; j++) c[mt][nt][j] = 0.f;

  for (int k0 = 0; k0 < K; k0 += 32) {
    float4 av[4], bv[4];
#pragma unroll
    for (int i = 0; i < 4; i++) {
      int id = tid + i * 256;
      int m = id >> 3;
      int k4 = (id & 7) << 2;
      av[i] = *(const float4*)&A[(size_t)(bm + m) * K + k0 + k4];
      bv[i] = *(const float4*)&Bw[(size_t)(bn + m) * K + k0 + k4];
    }
    __syncthreads();
#pragma unroll
    for (int i = 0; i < 4; i++) {
      int id = tid + i * 256;
      int m = id >> 3;
      int k4 = (id & 7) << 2;
      *(uint4*)&As[m * GST + k4] =
          make_uint4(f2tf(av[i].x), f2tf(av[i].y), f2tf(av[i].z), f2tf(av[i].w));
      *(uint4*)&Bs[m * GST + k4] =
          make_uint4(f2tf(bv[i].x), f2tf(bv[i].y), f2tf(bv[i].z), f2tf(bv[i].w));
    }
    __syncthreads();
#pragma unroll
    for (int kk = 0; kk < 4; kk++) {
      int k = kk * 8;
      uint32_t a[2][4];
#pragma unroll
      for (int mt = 0; mt < 2; mt++) {
        int mm = m0 + mt * 16 + g;
        a[mt][0] = As[mm * GST + k + tg];
        a[mt][1] = As[(mm + 8) * GST + k + tg];
        a[mt][2] = As[mm * GST + k + tg + 4];
        a[mt][3] = As[(mm + 8) * GST + k + tg + 4];
      }
#pragma unroll
      for (int nt = 0; nt < 8; nt++) {
        int nn = n0 + nt * 8 + g;
        uint32_t b0 = Bs[nn * GST + k + tg];
        uint32_t b1 = Bs[nn * GST + k + tg + 4];
        mma_tf32(c[0][nt], a[0][0], a[0][1], a[0][2], a[0][3], b0, b1);
        mma_tf32(c[1][nt], a[1][0], a[1][1], a[1][2], a[1][3], b0, b1);
      }
    }
  }

#pragma unroll
  for (int mt = 0; mt < 2; mt++)
#pragma unroll
    for (int nt = 0; nt < 8; nt++) {
      int row0 = bm + m0 + mt * 16 + g;
      int col = bn + n0 + nt * 8 + 2 * tg;
      float v0 = c[mt][nt][0], v1 = c[mt][nt][1];
      float v2 = c[mt][nt][2], v3 = c[mt][nt][3];
      if (RND) {
        v0 = __uint_as_float(f2tf(v0));
        v1 = __uint_as_float(f2tf(v1));
        v2 = __uint_as_float(f2tf(v2));
        v3 = __uint_as_float(f2tf(v3));
      }
      *(float2*)&C[(size_t)row0 * N + col] = make_float2(v0, v1);
      *(float2*)&C[(size_t)(row0 + 8) * N + col] = make_float2(v2, v3);
    }
}

// ---------------------------------------------------------------------------
// Attention, two-pass normalization, 32-row warp tiles.
// 4 warps/block (128 thr); each warp owns 32 Q-rows x all 64 K-cols, so
// B-fragments (K in QK, V rows in PV) are shared across two 16-row m-tiles
// (-40..50% smem bytes per mma vs 16-row tiles). exp+PV fused per k-step:
// PV step kk consumes only that kk's exponentials (et never materialized).
//  Pass A: QK-mma -> exp -> rowsum + PV accumulate. NO attn write.
//  Pass B: recompute S bitwise-identically, write normalized with __stcs.
// smem: Qs@0 (128x68), Ks@8704 (2x64x68), Vs@17408 (2x64x72) = 104KB.
// ---------------------------------------------------------------------------
#define AST 68
#define VST 72
#define QS_W 0
#define KS_W 8704
#define KS_STG 4352
#define VS_W 17408
#define VS_STG 4608
#define ATTN_SMEM (26624 * 4)

__global__ __launch_bounds__(128, 2) void attn_kernel(
    const float* __restrict__ Pq, const float* __restrict__ Pk,
    const float* __restrict__ Pv, float* __restrict__ attn,
    float* __restrict__ ctxT) {
  extern __shared__ float smf[];

  int tid = threadIdx.x, lane = tid & 31, wid = tid >> 5;
  int sub = lane >> 3, l7 = lane & 7;
  int g = lane >> 2, tg = lane & 3;
  int m0 = wid * 32;    // warp's 32 Q-rows (block-local)
  int qt = blockIdx.x;  // 0..15 (128-row Q tiles)
  int bh = blockIdx.y;
  int b = bh >> 4, h = bh & 15;

  const float* Qb = Pq + (size_t)b * SS * DM + (size_t)h * SS * DK;
  const float* Kb = Pk + (size_t)b * SS * DM + (size_t)h * SS * DK;
  const float* Vb = Pv + (size_t)b * SS * DM + (size_t)h * SS * DK;
  float* attn_b = attn + ((size_t)bh * SS + (size_t)qt * 128) * SS;

  uint32_t sbase = su(smf);

  // ldmatrix lane base byte offsets (two m-tiles per warp)
  uint32_t qOff0 =
      sbase + (QS_W + (m0 + (sub & 1) * 8 + l7) * AST + (sub >> 1) * 4) * 4;
  uint32_t qOff1 = qOff0 + 16 * AST * 4;
  uint32_t kLane = (((sub >> 1) * 8 + l7) * AST + (sub & 1) * 4) * 4;

  // cp.async chunk maps (128 threads)
  int qrow[16], qcol[16];
#pragma unroll
  for (int i = 0; i < 16; i++) {  // Q: 128 rows x 16 chunks
    int cc = tid + i * 128;
    qrow[i] = cc >> 4;
    qcol[i] = (cc & 15) << 2;
  }
  int crow[8], ccol[8];
#pragma unroll
  for (int i = 0; i < 8; i++) {  // K/V: 64 rows x 16 chunks
    int cc = tid + i * 128;
    crow[i] = cc >> 4;
    ccol[i] = (cc & 15) << 2;
  }

  // prologue: Q + K0 + V0 (one group)
#pragma unroll
  for (int i = 0; i < 16; i++)
    cpa16(sbase + (QS_W + qrow[i] * AST + qcol[i]) * 4,
          Qb + (size_t)(qt * 128 + qrow[i]) * DK + qcol[i]);
#pragma unroll
  for (int i = 0; i < 8; i++) {
    cpa16(sbase + (KS_W + crow[i] * AST + ccol[i]) * 4,
          Kb + (size_t)crow[i] * DK + ccol[i]);
    cpa16(sbase + (VS_W + crow[i] * VST + ccol[i]) * 4,
          Vb + (size_t)crow[i] * DK + ccol[i]);
  }
  cpcommit();

  float o[2][8][4];
#pragma unroll
  for (int mt = 0; mt < 2; mt++)
#pragma unroll
    for (int nt = 0; nt < 8; nt++)
#pragma unroll
      for (int j = 0; j < 4; j++) o[mt][nt][j] = 0.f;
  float racc[2][2] = {{0.f, 0.f}, {0.f, 0.f}};

  const int NT = SS / 64;

  // ================= Pass A: rowsums + PV (no attn write) =================
  for (int kt = 0; kt < NT; kt++) {
    int st = kt & 1;
    cpwait<0>();
    __syncthreads();  // stage st ready; everyone done reading st^1

    if (kt + 1 < NT) {
#pragma unroll
      for (int i = 0; i < 8; i++) {
        cpa16(sbase + (KS_W + (st ^ 1) * KS_STG + crow[i] * AST + ccol[i]) * 4,
              Kb + (size_t)((kt + 1) * 64 + crow[i]) * DK + ccol[i]);
        cpa16(sbase + (VS_W + (st ^ 1) * VS_STG + crow[i] * VST + ccol[i]) * 4,
              Vb + (size_t)((kt + 1) * 64 + crow[i]) * DK + ccol[i]);
      }
      cpcommit();
    }

    // S = Q K^T  (warp: 32 rows x 64 cols; B shared across both m-tiles)
    float s[2][8][4];
#pragma unroll
    for (int mt = 0; mt < 2; mt++)
#pragma unroll
      for (int nt = 0; nt < 8; nt++)
#pragma unroll
        for (int j = 0; j < 4; j++) s[mt][nt][j] = 0.f;
    uint32_t kBase = sbase + (KS_W + st * KS_STG) * 4 + kLane;
#pragma unroll
    for (int kk = 0; kk < 8; kk++) {
      uint32_t qa0[4], qa1[4];
      ldsm4(qa0[0], qa0[1], qa0[2], qa0[3], qOff0 + kk * 32);
      ldsm4(qa1[0], qa1[1], qa1[2], qa1[3], qOff1 + kk * 32);
#pragma unroll
      for (int p = 0; p < 4; p++) {
        uint32_t kb[4];
        ldsm4(kb[0], kb[1], kb[2], kb[3], kBase + p * 16 * AST * 4 + kk * 32);
        mma_tf32(s[0][2 * p], qa0[0], qa0[1], qa0[2], qa0[3], kb[0], kb[1]);
        mma_tf32(s[0][2 * p + 1], qa0[0], qa0[1], qa0[2], qa0[3], kb[2], kb[3]);
        mma_tf32(s[1][2 * p], qa1[0], qa1[1], qa1[2], qa1[3], kb[0], kb[1]);
        mma_tf32(s[1][2 * p + 1], qa1[0], qa1[1], qa1[2], qa1[3], kb[2], kb[3]);
      }
    }

    // fused exp + PV per k-step kk (PV step kk consumes only et(kk))
    int vsBase = VS_W + st * VS_STG;
#pragma unroll
    for (int kk = 0; kk < 8; kk++) {
      uint32_t a[2][4];
#pragma unroll
      for (int mt = 0; mt < 2; mt++) {
        float e0 = __expf(s[mt][kk][0] * 0.125f);
        float e1 = __expf(s[mt][kk][1] * 0.125f);
        float e2 = __expf(s[mt][kk][2] * 0.125f);
        float e3 = __expf(s[mt][kk][3] * 0.125f);
        racc[mt][0] += e0 + e1;
        racc[mt][1] += e2 + e3;
        uint32_t t0 = f2tf(e0), t1 = f2tf(e1), t2 = f2tf(e2), t3 = f2tf(e3);
        int qlo = tg >> 1, qhi = (tg >> 1) + 2;
        uint32_t lo0 = __shfl_sync(0xffffffffu, t0, qlo, 4);
        uint32_t lo1 = __shfl_sync(0xffffffffu, t1, qlo, 4);
        uint32_t lo2 = __shfl_sync(0xffffffffu, t2, qlo, 4);
        uint32_t lo3 = __shfl_sync(0xffffffffu, t3, qlo, 4);
        uint32_t hi0 = __shfl_sync(0xffffffffu, t0, qhi, 4);
        uint32_t hi1 = __shfl_sync(0xffffffffu, t1, qhi, 4);
        uint32_t hi2 = __shfl_sync(0xffffffffu, t2, qhi, 4);
        uint32_t hi3 = __shfl_sync(0xffffffffu, t3, qhi, 4);
        a[mt][0] = (tg & 1) ? lo1 : lo0;  // E[g][8kk+tg]
        a[mt][1] = (tg & 1) ? lo3 : lo2;  // E[g+8][8kk+tg]
        a[mt][2] = (tg & 1) ? hi1 : hi0;  // E[g][8kk+tg+4]
        a[mt][3] = (tg & 1) ? hi3 : hi2;  // E[g+8][8kk+tg+4]
      }
      int kr0 = vsBase + (kk * 8 + tg) * VST;
      int kr1 = vsBase + (kk * 8 + tg + 4) * VST;
#pragma unroll
      for (int nt = 0; nt < 8; nt++) {
        uint32_t b0 = __float_as_uint(smf[kr0 + nt * 8 + g]);
        uint32_t b1 = __float_as_uint(smf[kr1 + nt * 8 + g]);
        mma_tf32(o[0][nt], a[0][0], a[0][1], a[0][2], a[0][3], b0, b1);
        mma_tf32(o[1][nt], a[1][0], a[1][1], a[1][2], a[1][3], b0, b1);
      }
    }
  }

  // quad-reduce rowsums (rows are warp-private)
  float rl[2][2];
#pragma unroll
  for (int mt = 0; mt < 2; mt++)
#pragma unroll
    for (int i = 0; i < 2; i++) {
      float r = racc[mt][i];
      r += __shfl_xor_sync(0xffffffffu, r, 1);
      r += __shfl_xor_sync(0xffffffffu, r, 2);
      rl[mt][i] = 1.f / r;
    }

  // normalize ctx, write [b, s, h*64 + d]  (frees o[][] before pass B)
#pragma unroll
  for (int mt = 0; mt < 2; mt++) {
    int row0 = qt * 128 + m0 + mt * 16 + g, row1 = row0 + 8;
#pragma unroll
    for (int nt = 0; nt < 8; nt++) {
      int col = h * DK + nt * 8 + 2 * tg;
      *(float2*)&g_ctxT[(size_t)b * SS * DM + (size_t)row0 * DM + col] =
          make_float2(o[mt][nt][0] * rl[mt][0], o[mt][nt][1] * rl[mt][0]);
      *(float2*)&g_ctxT[(size_t)b * SS * DM + (size_t)row1 * DM + col] =
          make_float2(o[mt][nt][2] * rl[mt][1], o[mt][nt][3] * rl[mt][1]);
    }
  }
  (void)ctxT;

  // ======= Pass B: recompute S bitwise-identically, write normalized =======
#pragma unroll
  for (int i = 0; i < 8; i++)
    cpa16(sbase + (KS_W + crow[i] * AST + ccol[i]) * 4,
          Kb + (size_t)crow[i] * DK + ccol[i]);
  cpcommit();

  for (int kt = 0; kt < NT; kt++) {
    int st = kt & 1;
    cpwait<0>();
    __syncthreads();

    if (kt + 1 < NT) {
#pragma unroll
      for (int i = 0; i < 8; i++)
        cpa16(sbase + (KS_W + (st ^ 1) * KS_STG + crow[i] * AST + ccol[i]) * 4,
              Kb + (size_t)((kt + 1) * 64 + crow[i]) * DK + ccol[i]);
      cpcommit();
    }

    float s[2][8][4];
#pragma unroll
    for (int mt = 0; mt < 2; mt++)
#pragma unroll
      for (int nt = 0; nt < 8; nt++)
#pragma unroll
        for (int j = 0; j < 4; j++) s[mt][nt][j] = 0.f;
    uint32_t kBase = sbase + (KS_W + st * KS_STG) * 4 + kLane;
#pragma unroll
    for (int kk = 0; kk < 8; kk++) {
      uint32_t qa0[4], qa1[4];
      ldsm4(qa0[0], qa0[1], qa0[2], qa0[3], qOff0 + kk * 32);
      ldsm4(qa1[0], qa1[1], qa1[2], qa1[3], qOff1 + kk * 32);
#pragma unroll
      for (int p = 0; p < 4; p++) {
        uint32_t kb[4];
        ldsm4(kb[0], kb[1], kb[2], kb[3], kBase + p * 16 * AST * 4 + kk * 32);
        mma_tf32(s[0][2 * p], qa0[0], qa0[1], qa0[2], qa0[3], kb[0], kb[1]);
        mma_tf32(s[0][2 * p + 1], qa0[0], qa0[1], qa0[2], qa0[3], kb[2], kb[3]);
        mma_tf32(s[1][2 * p], qa1[0], qa1[1], qa1[2], qa1[3], kb[0], kb[1]);
        mma_tf32(s[1][2 * p + 1], qa1[0], qa1[1], qa1[2], qa1[3], kb[2], kb[3]);
      }
    }

#pragma unroll
    for (int mt = 0; mt < 2; mt++) {
      int row0 = m0 + mt * 16 + g, row1 = row0 + 8;
#pragma unroll
      for (int nt = 0; nt < 8; nt++) {
        float e0 = __expf(s[mt][nt][0] * 0.125f) * rl[mt][0];
        float e1 = __expf(s[mt][nt][1] * 0.125f) * rl[mt][0];
        float e2 = __expf(s[mt][nt][2] * 0.125f) * rl[mt][1];
        float e3 = __expf(s[mt][nt][3] * 0.125f) * rl[mt][1];
        int cc = nt * 8 + 2 * tg;
        __stcs((float2*)&attn_b[(size_t)row0 * SS + kt * 64 + cc],
               make_float2(e0, e1));
        __stcs((float2*)&attn_b[(size_t)row1 * SS + kt * 64 + cc],
               make_float2(e2, e3));
      }
    }
  }
}

// ---------------------------------------------------------------------------
// Residual add + LayerNorm, one block per row.
// ---------------------------------------------------------------------------
__global__ __launch_bounds__(256) void add_ln_kernel(
    const float* __restrict__ fc, const float* __restrict__ res,
    const float* __restrict__ gamma, const float* __restrict__ beta,
    float* __restrict__ out) {
  int row = blockIdx.x;
  int tid = threadIdx.x;
  float4 xf = ((const float4*)(fc + (size_t)row * DM))[tid];
  float4 xr = ((const float4*)(res + (size_t)row * DM))[tid];
  float x0 = xf.x + xr.x, x1 = xf.y + xr.y, x2 = xf.z + xr.z, x3 = xf.w + xr.w;
  float s = x0 + x1 + x2 + x3;
  float sq = x0 * x0 + x1 * x1 + x2 * x2 + x3 * x3;
#pragma unroll
  for (int o = 16; o; o >>= 1) {
    s += __shfl_down_sync(0xffffffffu, s, o);
    sq += __shfl_down_sync(0xffffffffu, sq, o);
  }
  __shared__ float ws[8], wq[8];
  __shared__ float mu_s, rs_s;
  if ((tid & 31) == 0) { ws[tid >> 5] = s; wq[tid >> 5] = sq; }
  __syncthreads();
  if (tid == 0) {
    float St = 0.f, Qt = 0.f;
#pragma unroll
    for (int i = 0; i < 8; i++) { St += ws[i]; Qt += wq[i]; }
    float mu = St * (1.f / DM);
    float var = Qt * (1.f / DM) - mu * mu;
    mu_s = mu;
    rs_s = rsqrtf(var + 1e-6f);
  }
  __syncthreads();
  float mu = mu_s, rs = rs_s;
  float4 g = ((const float4*)gamma)[tid];
  float4 bb = ((const float4*)beta)[tid];
  float4 o;
  o.x = (x0 - mu) * rs * g.x + bb.x;
  o.y = (x1 - mu) * rs * g.y + bb.y;
  o.z = (x2 - mu) * rs * g.z + bb.z;
  o.w = (x3 - mu) * rs * g.w + bb.w;
  ((float4*)(out + (size_t)row * DM))[tid] = o;
}

// ---------------------------------------------------------------------------
extern "C" void kernel_launch(void* const* d_in, const int* in_sizes, int n_in,
                              void* d_out, int out_size) {
  const float* q = (const float*)d_in[0];
  const float* k = (const float*)d_in[1];
  const float* v = (const float*)d_in[2];
  const float* w_qs = (const float*)d_in[3];
  const float* w_ks = (const float*)d_in[4];
  const float* w_vs = (const float*)d_in[5];
  const float* w_fc = (const float*)d_in[6];
  const float* gamma = (const float*)d_in[7];
  const float* beta = (const float*)d_in[8];
  float* out = (float*)d_out;

  const size_t out_elems = (size_t)BB * SS * DM;                // 8388608
  const size_t attn_elems = (size_t)BB * NH * SS * (size_t)SS;  // 268435456
  float* attn = ((size_t)out_size >= out_elems + attn_elems)
                    ? out + out_elems
                    : nullptr;

  float *Pq, *Pk, *Pv, *ctxT, *fcb, *attn_fb;
  cudaGetSymbolAddress((void**)&Pq, g_Pq);
  cudaGetSymbolAddress((void**)&Pk, g_Pk);
  cudaGetSymbolAddress((void**)&Pv, g_Pv);
  cudaGetSymbolAddress((void**)&ctxT, g_ctxT);
  cudaGetSymbolAddress((void**)&fcb, g_fc);
  cudaGetSymbolAddress((void**)&attn_fb, g_attn_fallback);
  if (!attn) attn = attn_fb;

  cudaFuncSetAttribute(attn_kernel,
                       cudaFuncAttributeMaxDynamicSharedMemorySize, ATTN_SMEM);

  dim3 gproj(DM / 128, (BB * SS) / 128);  // (8, 64)
  gemm_tf32_nt<true><<<gproj, 256>>>(q, w_qs, Pq, BB * SS, DM, DM);
  gemm_tf32_nt<true><<<gproj, 256>>>(k, w_ks, Pk, BB * SS, DM, DM);
  gemm_tf32_nt<true><<<gproj, 256>>>(v, w_vs, Pv, BB * SS, DM, DM);

  attn_kernel<<<dim3(SS / 128, BB * NH), 128, ATTN_SMEM>>>(Pq, Pk, Pv, attn,
                                                           ctxT);

  gemm_tf32_nt<false><<<gproj, 256>>>(ctxT, w_fc, fcb, BB * SS, DM, DM);
  add_ln_kernel<<<BB * SS, 256>>>(fcb, q, gamma, beta, out);
}